// round 1
// baseline (speedup 1.0000x reference)
#include <cuda_runtime.h>
#include <math.h>

// Problem constants (fixed by dataset)
#define N_NODES 20000
#define E_EDGES 200000
#define ET_EDGES 40000
#define DIN 8
#define HDIM 128
#define NEA 7
#define HC 896          // 7*128
#define HLDIM 128
#define OUTD 4

// ---------------- scratch (static device globals; no runtime allocation) ----------------
static __device__ float g_ew[E_EDGES];
static __device__ float g_dis[8 * N_NODES];            // 7 attr channels + 1 ew channel
static __device__ float g_W0r[DIN * HC];
static __device__ float g_W2r[HDIM * HC];
static __device__ float g_W3r[HC * HC];
static __device__ float g_hw[(size_t)N_NODES * HC];    // h@W scratch (wide)
static __device__ float g_hw128[(size_t)N_NODES * HDIM];
static __device__ float g_x1[(size_t)N_NODES * HC];
static __device__ float g_xb2[(size_t)N_NODES * HDIM];
static __device__ float g_x3[(size_t)N_NODES * HC];
static __device__ float g_x4[(size_t)N_NODES * HC];
static __device__ float g_U[(size_t)N_NODES * HDIM];
static __device__ float g_V[(size_t)N_NODES * HDIM];
static __device__ float g_Ha[(size_t)2 * ET_EDGES * HLDIM];
static __device__ float g_Hb[(size_t)2 * ET_EDGES * HLDIM];
static __device__ float g_T[(size_t)2 * ET_EDGES * OUTD];

// ---------------- helpers ----------------
__device__ __forceinline__ void redAdd4(float* p, float4 v) {
    // sm_90+: vectored global float reduction (no return) — 4x fewer REDG ops
    asm volatile("red.global.add.v4.f32 [%0], {%1,%2,%3,%4};"
                 :: "l"(p), "f"(v.x), "f"(v.y), "f"(v.z), "f"(v.w) : "memory");
}

// ---------------- edge-weight MLP: [E,7] -> sigmoid scalar ----------------
__global__ __launch_bounds__(256) void edge_mlp_kernel(
    const float* __restrict__ ea,
    const float* __restrict__ w1, const float* __restrict__ bb1,
    const float* __restrict__ w2, const float* __restrict__ bb2,
    const float* __restrict__ w3, const float* __restrict__ bb3,
    float* __restrict__ out, int E)
{
    __shared__ float s1[NEA * 28], sb1[28], s2[28 * 28], sb2[28], s3[28], sb3v[1];
    for (int i = threadIdx.x; i < NEA * 28; i += blockDim.x) s1[i] = w1[i];
    for (int i = threadIdx.x; i < 28; i += blockDim.x) { sb1[i] = bb1[i]; sb2[i] = bb2[i]; s3[i] = w3[i]; }
    for (int i = threadIdx.x; i < 28 * 28; i += blockDim.x) s2[i] = w2[i];
    if (threadIdx.x == 0) sb3v[0] = bb3[0];
    __syncthreads();

    int e = blockIdx.x * blockDim.x + threadIdx.x;
    if (e >= E) return;
    float a[NEA];
#pragma unroll
    for (int k = 0; k < NEA; k++) a[k] = ea[(size_t)e * NEA + k];
    float t[28];
#pragma unroll
    for (int j = 0; j < 28; j++) {
        float v = sb1[j];
#pragma unroll
        for (int k = 0; k < NEA; k++) v += a[k] * s1[k * 28 + j];
        t[j] = fmaxf(v, 0.f);
    }
    float u[28];
#pragma unroll
    for (int j = 0; j < 28; j++) {
        float v = sb2[j];
#pragma unroll
        for (int k = 0; k < 28; k++) v += t[k] * s2[k * 28 + j];
        u[j] = fmaxf(v, 0.f);
    }
    float z = sb3v[0];
#pragma unroll
    for (int k = 0; k < 28; k++) z += u[k] * s3[k];
    out[e] = 1.f / (1.f + expf(-z));
}

// ---------------- degree / normalization ----------------
__global__ void deg_init_kernel(float* __restrict__ deg, int n) {
    int i = blockIdx.x * blockDim.x + threadIdx.x;
    if (i < n) deg[i] = 1.0f;   // self-loop weight 1
}

__global__ void deg_accum_kernel(const int* __restrict__ ei, const float* __restrict__ ea,
                                 const float* __restrict__ ew, float* __restrict__ deg, int E, int N)
{
    int e = blockIdx.x * blockDim.x + threadIdx.x;
    if (e >= E) return;
    int c = ei[E + e];
#pragma unroll
    for (int i = 0; i < NEA; i++) atomicAdd(&deg[i * N + c], ea[(size_t)e * NEA + i]);
    atomicAdd(&deg[NEA * N + c], ew[e]);
}

__global__ void deg_rsqrt_kernel(float* __restrict__ deg, int n) {
    int i = blockIdx.x * blockDim.x + threadIdx.x;
    if (i < n) deg[i] = rsqrtf(deg[i]);   // deg >= 1 always
}

// ---------------- weight pack: [7,K,128] -> [K,896] ----------------
__global__ void pack_w_kernel(const float* __restrict__ in, float* __restrict__ out, int K) {
    int idx = blockIdx.x * blockDim.x + threadIdx.x;
    int total = K * HC;
    if (idx >= total) return;
    int k = idx / HC, c = idx % HC;
    int i = c >> 7, j = c & 127;
    out[idx] = in[((size_t)i * K + k) * HDIM + j];
}

// ---------------- G0: x[N,8] @ W0r[8,896] ----------------
__global__ void gemm_k8_kernel(const float* __restrict__ x, const float* __restrict__ W,
                               float* __restrict__ out)
{
    int idx = blockIdx.x * blockDim.x + threadIdx.x;
    if (idx >= N_NODES * HC) return;
    int m = idx / HC, c = idx % HC;
    float v = 0.f;
#pragma unroll
    for (int k = 0; k < DIN; k++) v += __ldg(&x[m * DIN + k]) * W[k * HC + c];
    out[idx] = v;
}

// ---------------- init accumulator: bias + self-loop message ----------------
// out[v,c] = bias[c] + dis[i][v]^2 * hw[v,c]   (i = c/128 within the dis block given)
__global__ void init_self_kernel(const float* __restrict__ hw, const float* __restrict__ bias,
                                 const float* __restrict__ dis, float* __restrict__ out, int C)
{
    size_t idx = (size_t)blockIdx.x * blockDim.x + threadIdx.x;
    if (idx >= (size_t)N_NODES * C) return;
    int v = (int)(idx / C), c = (int)(idx % C);
    int i = c >> 7;
    float d = dis[i * N_NODES + v];
    out[idx] = bias[c] + d * d * hw[idx];
}

// ---------------- scatter, 7-channel wide (C=896): one warp per edge ----------------
__global__ __launch_bounds__(256) void scatter7_kernel(
    const float* __restrict__ hw, float* __restrict__ out,
    const int* __restrict__ ei, const float* __restrict__ ea,
    const float* __restrict__ dis, int E)
{
    int w = (blockIdx.x * blockDim.x + threadIdx.x) >> 5;
    int lane = threadIdx.x & 31;
    if (w >= E) return;
    int r = __ldg(&ei[w]);
    int c = __ldg(&ei[E + w]);
    const float* hrow = hw + (size_t)r * HC;
    float* orow = out + (size_t)c * HC;
#pragma unroll
    for (int i = 0; i < NEA; i++) {
        float coef = __ldg(&dis[i * N_NODES + r]) * __ldg(&dis[i * N_NODES + c]) * __ldg(&ea[(size_t)w * NEA + i]);
        float4 v = *(const float4*)(hrow + i * HDIM + lane * 4);
        v.x *= coef; v.y *= coef; v.z *= coef; v.w *= coef;
        redAdd4(orow + i * HDIM + lane * 4, v);
    }
}

// ---------------- scatter, single-channel (C=128, ew norm) ----------------
__global__ __launch_bounds__(256) void scatter1_kernel(
    const float* __restrict__ hw, float* __restrict__ out,
    const int* __restrict__ ei, const float* __restrict__ ew,
    const float* __restrict__ dis, int E)   // dis pre-offset to channel 7
{
    int w = (blockIdx.x * blockDim.x + threadIdx.x) >> 5;
    int lane = threadIdx.x & 31;
    if (w >= E) return;
    int r = __ldg(&ei[w]);
    int c = __ldg(&ei[E + w]);
    float coef = __ldg(&dis[r]) * __ldg(&dis[c]) * __ldg(&ew[w]);
    float4 v = *(const float4*)(hw + (size_t)r * HDIM + lane * 4);
    v.x *= coef; v.y *= coef; v.z *= coef; v.w *= coef;
    redAdd4(out + (size_t)c * HDIM + lane * 4, v);
}

__global__ void relu_kernel(float* __restrict__ p, size_t n) {
    size_t i = (size_t)blockIdx.x * blockDim.x + threadIdx.x;
    if (i < n) p[i] = fmaxf(p[i], 0.f);
}

// ---------------- general SGEMM: C[M,Nc] = A[M,K] @ B[K,Nc] (+bias)(+relu) ----------------
// BM=128, BN=64, BK=16, 256 threads, 8x4 per thread. K%16==0, Nc%64==0, M guarded.
#define BM 128
#define BN 64
#define BK 16
__global__ __launch_bounds__(256) void sgemm_kernel(
    const float* __restrict__ A, const float* __restrict__ B, float* __restrict__ C,
    int M, int K, int Nc, const float* __restrict__ bias, int doRelu)
{
    __shared__ float As[BK][BM];
    __shared__ float Bs[BK][BN];
    int tid = threadIdx.x;
    int rowBase = blockIdx.y * BM;
    int colBase = blockIdx.x * BN;
    int ty = tid >> 4, tx = tid & 15;

    float acc[8][4];
#pragma unroll
    for (int i = 0; i < 8; i++)
#pragma unroll
        for (int j = 0; j < 4; j++) acc[i][j] = 0.f;

    int aRow0 = tid >> 2;          // 0..63
    int aCol  = (tid & 3) * 4;     // 0,4,8,12
    int bRow  = tid >> 4;          // 0..15
    int bCol  = (tid & 15) * 4;    // 0..60

    for (int k0 = 0; k0 < K; k0 += BK) {
#pragma unroll
        for (int h = 0; h < 2; h++) {
            int r = rowBase + aRow0 + h * 64;
            float4 av = make_float4(0.f, 0.f, 0.f, 0.f);
            if (r < M) av = *(const float4*)(A + (size_t)r * K + k0 + aCol);
            As[aCol + 0][aRow0 + h * 64] = av.x;
            As[aCol + 1][aRow0 + h * 64] = av.y;
            As[aCol + 2][aRow0 + h * 64] = av.z;
            As[aCol + 3][aRow0 + h * 64] = av.w;
        }
        float4 bv = *(const float4*)(B + (size_t)(k0 + bRow) * Nc + colBase + bCol);
        *(float4*)&Bs[bRow][bCol] = bv;
        __syncthreads();

#pragma unroll
        for (int kk = 0; kk < BK; kk++) {
            float4 a0 = *(const float4*)&As[kk][ty * 8];
            float4 a1 = *(const float4*)&As[kk][ty * 8 + 4];
            float4 b  = *(const float4*)&Bs[kk][tx * 4];
            float ar[8] = {a0.x, a0.y, a0.z, a0.w, a1.x, a1.y, a1.z, a1.w};
            float br[4] = {b.x, b.y, b.z, b.w};
#pragma unroll
            for (int i = 0; i < 8; i++)
#pragma unroll
                for (int j = 0; j < 4; j++) acc[i][j] += ar[i] * br[j];
        }
        __syncthreads();
    }

#pragma unroll
    for (int i = 0; i < 8; i++) {
        int r = rowBase + ty * 8 + i;
        if (r >= M) continue;
#pragma unroll
        for (int j = 0; j < 4; j++) {
            int c = colBase + tx * 4 + j;
            float v = acc[i][j];
            if (bias) v += bias[c];
            if (doRelu) v = fmaxf(v, 0.f);
            C[(size_t)r * Nc + c] = v;
        }
    }
}

// ---------------- link head ----------------
// H0[e,j] = relu(U[a]+V[b]+lb0[j]); first ET rows fwd (a=s,b=d), next ET rev (a=d,b=s)
__global__ void build_h0_kernel(const float* __restrict__ U, const float* __restrict__ V,
                                const float* __restrict__ lb0, const int* __restrict__ eit,
                                float* __restrict__ Hout)
{
    size_t idx = (size_t)blockIdx.x * blockDim.x + threadIdx.x;
    if (idx >= (size_t)2 * ET_EDGES * HLDIM) return;
    int e = (int)(idx >> 7);
    int j = (int)(idx & 127);
    int a, b;
    if (e < ET_EDGES) { a = eit[e]; b = eit[ET_EDGES + e]; }
    else              { int e2 = e - ET_EDGES; a = eit[ET_EDGES + e2]; b = eit[e2]; }
    float v = U[(size_t)a * HLDIM + j] + V[(size_t)b * HLDIM + j] + lb0[j];
    Hout[idx] = fmaxf(v, 0.f);
}

// final layer: T[m,0..3] = H[m,:] @ lw4 + lb4 ; warp per row
__global__ __launch_bounds__(256) void gemm_out_kernel(
    const float* __restrict__ Hm, const float* __restrict__ lw4,
    const float* __restrict__ lb4, float* __restrict__ T, int M)
{
    int w = (blockIdx.x * blockDim.x + threadIdx.x) >> 5;
    int lane = threadIdx.x & 31;
    if (w >= M) return;
    float h0 = Hm[(size_t)w * HLDIM + lane];
    float h1 = Hm[(size_t)w * HLDIM + 32 + lane];
    float h2 = Hm[(size_t)w * HLDIM + 64 + lane];
    float h3 = Hm[(size_t)w * HLDIM + 96 + lane];
    float acc[4];
#pragma unroll
    for (int c = 0; c < 4; c++) {
        acc[c] = h0 * __ldg(&lw4[lane * 4 + c])
               + h1 * __ldg(&lw4[(lane + 32) * 4 + c])
               + h2 * __ldg(&lw4[(lane + 64) * 4 + c])
               + h3 * __ldg(&lw4[(lane + 96) * 4 + c]);
    }
#pragma unroll
    for (int off = 16; off > 0; off >>= 1)
#pragma unroll
        for (int c = 0; c < 4; c++) acc[c] += __shfl_down_sync(0xffffffffu, acc[c], off);
    if (lane == 0) {
#pragma unroll
        for (int c = 0; c < 4; c++) T[(size_t)w * 4 + c] = acc[c] + lb4[c];
    }
}

// out[e,c] = 0.5*(T[e,c] + T[ET+e, perm[c]]), perm = [0,2,1,3]
__global__ void combine_kernel(const float* __restrict__ T, float* __restrict__ out) {
    int idx = blockIdx.x * blockDim.x + threadIdx.x;
    if (idx >= ET_EDGES * 4) return;
    int e = idx >> 2, c = idx & 3;
    int pc = (c == 1) ? 2 : (c == 2) ? 1 : c;
    out[idx] = 0.5f * (T[(size_t)e * 4 + c] + T[(size_t)(ET_EDGES + e) * 4 + pc]);
}

// ---------------- host orchestration ----------------
static inline int cdiv(size_t a, int b) { return (int)((a + b - 1) / b); }

extern "C" void kernel_launch(void* const* d_in, const int* in_sizes, int n_in,
                              void* d_out, int out_size)
{
    const float* x    = (const float*)d_in[0];
    const int*   ei   = (const int*)  d_in[1];
    const float* ea   = (const float*)d_in[2];
    const int*   eit  = (const int*)  d_in[3];
    const float* W0   = (const float*)d_in[4];
    const float* b0   = (const float*)d_in[5];
    const float* W1   = (const float*)d_in[6];
    const float* b1   = (const float*)d_in[7];
    const float* W2   = (const float*)d_in[8];
    const float* b2   = (const float*)d_in[9];
    const float* W3   = (const float*)d_in[10];
    const float* b3   = (const float*)d_in[11];
    const float* ew1  = (const float*)d_in[12];
    const float* eb1  = (const float*)d_in[13];
    const float* ew2  = (const float*)d_in[14];
    const float* eb2  = (const float*)d_in[15];
    const float* ew3  = (const float*)d_in[16];
    const float* eb3  = (const float*)d_in[17];
    const float* lw0  = (const float*)d_in[18];
    const float* lb0  = (const float*)d_in[19];
    const float* lwh  = (const float*)d_in[20];
    const float* lbh  = (const float*)d_in[21];
    const float* lw4  = (const float*)d_in[22];
    const float* lb4  = (const float*)d_in[23];
    float* out = (float*)d_out;

    float *ew, *dis, *W0r, *W2r, *W3r, *hw, *hw128, *x1, *x2b, *x3, *x4, *U, *V, *Ha, *Hb, *T;
    cudaGetSymbolAddress((void**)&ew,    g_ew);
    cudaGetSymbolAddress((void**)&dis,   g_dis);
    cudaGetSymbolAddress((void**)&W0r,   g_W0r);
    cudaGetSymbolAddress((void**)&W2r,   g_W2r);
    cudaGetSymbolAddress((void**)&W3r,   g_W3r);
    cudaGetSymbolAddress((void**)&hw,    g_hw);
    cudaGetSymbolAddress((void**)&hw128, g_hw128);
    cudaGetSymbolAddress((void**)&x1,    g_x1);
    cudaGetSymbolAddress((void**)&x2b,   g_xb2);
    cudaGetSymbolAddress((void**)&x3,    g_x3);
    cudaGetSymbolAddress((void**)&x4,    g_x4);
    cudaGetSymbolAddress((void**)&U,     g_U);
    cudaGetSymbolAddress((void**)&V,     g_V);
    cudaGetSymbolAddress((void**)&Ha,    g_Ha);
    cudaGetSymbolAddress((void**)&Hb,    g_Hb);
    cudaGetSymbolAddress((void**)&T,     g_T);

    const int TB = 256;
    const size_t NW = (size_t)N_NODES * HC;    // wide node tensor elems
    const size_t NN = (size_t)N_NODES * HDIM;  // narrow

    // 1) edge-weight MLP
    edge_mlp_kernel<<<cdiv(E_EDGES, TB), TB>>>(ea, ew1, eb1, ew2, eb2, ew3, eb3, ew, E_EDGES);

    // 2) degrees -> dis = rsqrt(deg) for 8 channels
    deg_init_kernel<<<cdiv(8 * N_NODES, TB), TB>>>(dis, 8 * N_NODES);
    deg_accum_kernel<<<cdiv(E_EDGES, TB), TB>>>(ei, ea, ew, dis, E_EDGES, N_NODES);
    deg_rsqrt_kernel<<<cdiv(8 * N_NODES, TB), TB>>>(dis, 8 * N_NODES);

    // 3) pack weights to [K, 896]
    pack_w_kernel<<<cdiv(DIN * HC, TB), TB>>>(W0, W0r, DIN);
    pack_w_kernel<<<cdiv(HDIM * HC, TB), TB>>>(W2, W2r, HDIM);
    pack_w_kernel<<<cdiv(HC * HC, TB), TB>>>(W3, W3r, HC);

    // ---- layer 1 ----
    gemm_k8_kernel<<<cdiv(NW, TB), TB>>>(x, W0r, hw);
    init_self_kernel<<<cdiv(NW, TB), TB>>>(hw, b0, dis, x1, HC);
    scatter7_kernel<<<cdiv((size_t)E_EDGES * 32, TB), TB>>>(hw, x1, ei, ea, dis, E_EDGES);
    relu_kernel<<<cdiv(NW, TB), TB>>>(x1, NW);

    // ---- layer 2 (ew norm) ----
    {
        dim3 g(HDIM / BN, cdiv(N_NODES, BM));
        sgemm_kernel<<<g, 256>>>(x1, W1, hw128, N_NODES, HC, HDIM, nullptr, 0);
    }
    init_self_kernel<<<cdiv(NN, TB), TB>>>(hw128, b1, dis + NEA * N_NODES, x2b, HDIM);
    scatter1_kernel<<<cdiv((size_t)E_EDGES * 32, TB), TB>>>(hw128, x2b, ei, ew, dis + NEA * N_NODES, E_EDGES);
    relu_kernel<<<cdiv(NN, TB), TB>>>(x2b, NN);

    // ---- layer 3 ----
    {
        dim3 g(HC / BN, cdiv(N_NODES, BM));
        sgemm_kernel<<<g, 256>>>(x2b, W2r, hw, N_NODES, HDIM, HC, nullptr, 0);
    }
    init_self_kernel<<<cdiv(NW, TB), TB>>>(hw, b2, dis, x3, HC);
    scatter7_kernel<<<cdiv((size_t)E_EDGES * 32, TB), TB>>>(hw, x3, ei, ea, dis, E_EDGES);
    relu_kernel<<<cdiv(NW, TB), TB>>>(x3, NW);

    // ---- layer 4 ----
    {
        dim3 g(HC / BN, cdiv(N_NODES, BM));
        sgemm_kernel<<<g, 256>>>(x3, W3r, hw, N_NODES, HC, HC, nullptr, 0);
    }
    init_self_kernel<<<cdiv(NW, TB), TB>>>(hw, b3, dis, x4, HC);
    scatter7_kernel<<<cdiv((size_t)E_EDGES * 32, TB), TB>>>(hw, x4, ei, ea, dis, E_EDGES);
    relu_kernel<<<cdiv(NW, TB), TB>>>(x4, NW);

    // ---- link head: U = x4 @ lw0_top, V = x4 @ lw0_bot ----
    {
        dim3 g(HDIM / BN, cdiv(N_NODES, BM));
        sgemm_kernel<<<g, 256>>>(x4, lw0, U, N_NODES, HC, HDIM, nullptr, 0);
        sgemm_kernel<<<g, 256>>>(x4, lw0 + (size_t)HC * HDIM, V, N_NODES, HC, HDIM, nullptr, 0);
    }

    const int M2 = 2 * ET_EDGES;
    build_h0_kernel<<<cdiv((size_t)M2 * HLDIM, TB), TB>>>(U, V, lb0, eit, Ha);

    // 3 hidden layers with bias+relu fused
    {
        dim3 g(HLDIM / BN, cdiv(M2, BM));
        sgemm_kernel<<<g, 256>>>(Ha, lwh,                 Hb, M2, HLDIM, HLDIM, lbh,       1);
        sgemm_kernel<<<g, 256>>>(Hb, lwh + 128 * 128,     Ha, M2, HLDIM, HLDIM, lbh + 128, 1);
        sgemm_kernel<<<g, 256>>>(Ha, lwh + 2 * 128 * 128, Hb, M2, HLDIM, HLDIM, lbh + 256, 1);
    }

    gemm_out_kernel<<<cdiv((size_t)M2 * 32, TB), TB>>>(Hb, lw4, lb4, T, M2);
    combine_kernel<<<cdiv(ET_EDGES * 4, TB), TB>>>(T, out);
}

// round 2
// speedup vs baseline: 1.0014x; 1.0014x over previous
#include <cuda_runtime.h>
#include <math.h>

// Problem constants (fixed by dataset)
#define N_NODES 20000
#define E_EDGES 200000
#define ET_EDGES 40000
#define DIN 8
#define HDIM 128
#define NEA 7
#define HC 896          // 7*128
#define HLDIM 128
#define OUTD 4

// ---------------- scratch (static device globals; no runtime allocation) ----------------
static __device__ float g_ew[E_EDGES];
static __device__ float g_dis[8 * N_NODES];            // 7 attr channels + 1 ew channel
static __device__ float g_W0r[DIN * HC];
static __device__ float g_W2r[HDIM * HC];
static __device__ float g_W3r[HC * HC];
static __device__ float g_Wuv[HC * 256];
static __device__ float g_hw[(size_t)N_NODES * HC];    // h@W scratch (wide)
static __device__ float g_hw128[(size_t)N_NODES * HDIM];
static __device__ float g_x1[(size_t)N_NODES * HC];
static __device__ float g_xb2[(size_t)N_NODES * HDIM];
static __device__ float g_x3[(size_t)N_NODES * HC];
static __device__ float g_x4[(size_t)N_NODES * HC];
static __device__ float g_UV[(size_t)N_NODES * 256];
static __device__ float g_Ha[(size_t)2 * ET_EDGES * HLDIM];
static __device__ float g_Hb[(size_t)2 * ET_EDGES * HLDIM];
static __device__ float g_T[(size_t)2 * ET_EDGES * OUTD];

// ---------------- helpers ----------------
__device__ __forceinline__ void redAdd4(float* p, float4 v) {
    asm volatile("red.global.add.v4.f32 [%0], {%1,%2,%3,%4};"
                 :: "l"(p), "f"(v.x), "f"(v.y), "f"(v.z), "f"(v.w) : "memory");
}

// ---------------- edge-weight MLP: [E,7] -> sigmoid scalar ----------------
__global__ __launch_bounds__(256) void edge_mlp_kernel(
    const float* __restrict__ ea,
    const float* __restrict__ w1, const float* __restrict__ bb1,
    const float* __restrict__ w2, const float* __restrict__ bb2,
    const float* __restrict__ w3, const float* __restrict__ bb3,
    float* __restrict__ out, int E)
{
    __shared__ float s1[NEA * 28], sb1[28], s2[28 * 28], sb2[28], s3[28], sb3v[1];
    for (int i = threadIdx.x; i < NEA * 28; i += blockDim.x) s1[i] = w1[i];
    for (int i = threadIdx.x; i < 28; i += blockDim.x) { sb1[i] = bb1[i]; sb2[i] = bb2[i]; s3[i] = w3[i]; }
    for (int i = threadIdx.x; i < 28 * 28; i += blockDim.x) s2[i] = w2[i];
    if (threadIdx.x == 0) sb3v[0] = bb3[0];
    __syncthreads();

    int e = blockIdx.x * blockDim.x + threadIdx.x;
    if (e >= E) return;
    float a[NEA];
#pragma unroll
    for (int k = 0; k < NEA; k++) a[k] = ea[(size_t)e * NEA + k];
    float t[28];
#pragma unroll
    for (int j = 0; j < 28; j++) {
        float v = sb1[j];
#pragma unroll
        for (int k = 0; k < NEA; k++) v += a[k] * s1[k * 28 + j];
        t[j] = fmaxf(v, 0.f);
    }
    float u[28];
#pragma unroll
    for (int j = 0; j < 28; j++) {
        float v = sb2[j];
#pragma unroll
        for (int k = 0; k < 28; k++) v += t[k] * s2[k * 28 + j];
        u[j] = fmaxf(v, 0.f);
    }
    float z = sb3v[0];
#pragma unroll
    for (int k = 0; k < 28; k++) z += u[k] * s3[k];
    out[e] = 1.f / (1.f + expf(-z));
}

// ---------------- degree / normalization ----------------
__global__ void deg_init_kernel(float* __restrict__ deg, int n) {
    int i = blockIdx.x * blockDim.x + threadIdx.x;
    if (i < n) deg[i] = 1.0f;   // self-loop weight 1
}

__global__ void deg_accum_kernel(const int* __restrict__ ei, const float* __restrict__ ea,
                                 const float* __restrict__ ew, float* __restrict__ deg, int E, int N)
{
    int e = blockIdx.x * blockDim.x + threadIdx.x;
    if (e >= E) return;
    int c = ei[E + e];
#pragma unroll
    for (int i = 0; i < NEA; i++) atomicAdd(&deg[i * N + c], ea[(size_t)e * NEA + i]);
    atomicAdd(&deg[NEA * N + c], ew[e]);
}

__global__ void deg_rsqrt_kernel(float* __restrict__ deg, int n) {
    int i = blockIdx.x * blockDim.x + threadIdx.x;
    if (i < n) deg[i] = rsqrtf(deg[i]);   // deg >= 1 always
}

// ---------------- weight pack: [7,K,128] -> [K,896] ----------------
__global__ void pack_w_kernel(const float* __restrict__ in, float* __restrict__ out, int K) {
    int idx = blockIdx.x * blockDim.x + threadIdx.x;
    int total = K * HC;
    if (idx >= total) return;
    int k = idx / HC, c = idx % HC;
    int i = c >> 7, j = c & 127;
    out[idx] = in[((size_t)i * K + k) * HDIM + j];
}

// pack lw0 [2*HC,128] -> Wuv [HC,256]  (cols 0-127 = U weights, 128-255 = V weights)
__global__ void pack_uv_kernel(const float* __restrict__ lw0, float* __restrict__ out) {
    int idx = blockIdx.x * blockDim.x + threadIdx.x;
    if (idx >= HC * 256) return;
    int k = idx >> 8, c = idx & 255;
    out[idx] = (c < 128) ? lw0[(size_t)k * 128 + c]
                         : lw0[(size_t)(HC + k) * 128 + (c - 128)];
}

// ---------------- G0: x[N,8] @ W0r[8,896] ----------------
__global__ void gemm_k8_kernel(const float* __restrict__ x, const float* __restrict__ W,
                               float* __restrict__ out)
{
    int idx = blockIdx.x * blockDim.x + threadIdx.x;
    if (idx >= N_NODES * HC) return;
    int m = idx / HC, c = idx % HC;
    float v = 0.f;
#pragma unroll
    for (int k = 0; k < DIN; k++) v += __ldg(&x[m * DIN + k]) * W[k * HC + c];
    out[idx] = v;
}

// ---------------- init accumulator: bias + self-loop message ----------------
__global__ void init_self_kernel(const float* __restrict__ hw, const float* __restrict__ bias,
                                 const float* __restrict__ dis, float* __restrict__ out, int C)
{
    size_t idx = (size_t)blockIdx.x * blockDim.x + threadIdx.x;
    if (idx >= (size_t)N_NODES * C) return;
    int v = (int)(idx / C), c = (int)(idx % C);
    int i = c >> 7;
    float d = dis[i * N_NODES + v];
    out[idx] = bias[c] + d * d * hw[idx];
}

// ---------------- scatter, 7-channel wide (C=896): one warp per edge ----------------
__global__ __launch_bounds__(256) void scatter7_kernel(
    const float* __restrict__ hw, float* __restrict__ out,
    const int* __restrict__ ei, const float* __restrict__ ea,
    const float* __restrict__ dis, int E)
{
    int w = (blockIdx.x * blockDim.x + threadIdx.x) >> 5;
    int lane = threadIdx.x & 31;
    if (w >= E) return;
    int r = __ldg(&ei[w]);
    int c = __ldg(&ei[E + w]);
    const float* hrow = hw + (size_t)r * HC;
    float* orow = out + (size_t)c * HC;
#pragma unroll
    for (int i = 0; i < NEA; i++) {
        float coef = __ldg(&dis[i * N_NODES + r]) * __ldg(&dis[i * N_NODES + c]) * __ldg(&ea[(size_t)w * NEA + i]);
        float4 v = *(const float4*)(hrow + i * HDIM + lane * 4);
        v.x *= coef; v.y *= coef; v.z *= coef; v.w *= coef;
        redAdd4(orow + i * HDIM + lane * 4, v);
    }
}

// ---------------- scatter, single-channel (C=128, ew norm) ----------------
__global__ __launch_bounds__(256) void scatter1_kernel(
    const float* __restrict__ hw, float* __restrict__ out,
    const int* __restrict__ ei, const float* __restrict__ ew,
    const float* __restrict__ dis, int E)   // dis pre-offset to channel 7
{
    int w = (blockIdx.x * blockDim.x + threadIdx.x) >> 5;
    int lane = threadIdx.x & 31;
    if (w >= E) return;
    int r = __ldg(&ei[w]);
    int c = __ldg(&ei[E + w]);
    float coef = __ldg(&dis[r]) * __ldg(&dis[c]) * __ldg(&ew[w]);
    float4 v = *(const float4*)(hw + (size_t)r * HDIM + lane * 4);
    v.x *= coef; v.y *= coef; v.z *= coef; v.w *= coef;
    redAdd4(out + (size_t)c * HDIM + lane * 4, v);
}

// ---------------- SGEMM: C[M,Nc] = op(A)[M,K] @ B[K,Nc] (+bias)(+relu) ----------------
// BM=BN=128, BK=16, 256 threads, 8x8 per thread, double-buffered smem.
// Requirements: K%16==0, Nc%128==0; M guarded. flags: bit0 = relu output, bit1 = relu on A load.
#define BM 128
#define BN 128
#define BK 16
__global__ __launch_bounds__(256) void sgemm_kernel(
    const float* __restrict__ A, const float* __restrict__ B, float* __restrict__ C,
    int M, int K, int Nc, const float* __restrict__ bias, int flags)
{
    __shared__ float As[2][BK][BM];
    __shared__ float Bs[2][BK][BN];

    const int tid = threadIdx.x;
    const int rowBase = blockIdx.y * BM;
    const int colBase = blockIdx.x * BN;
    const bool reluA = (flags & 2) != 0;

    const int aRow = tid >> 2;            // 0..63
    const int aCol = (tid & 3) << 2;      // 0,4,8,12
    const int bRow = tid >> 5;            // 0..7
    const int bCol = (tid & 31) << 2;     // 0..124

    const int ty = tid >> 4;              // 0..15 -> rows ty*8..ty*8+7
    const int tx = tid & 15;              // 0..15 -> cols tx*8..tx*8+7

    float acc[8][8];
#pragma unroll
    for (int i = 0; i < 8; i++)
#pragma unroll
        for (int j = 0; j < 8; j++) acc[i][j] = 0.f;

    const int r0 = rowBase + aRow;
    const int r1 = rowBase + aRow + 64;

    // ---- prologue: load tile k0=0 into buffer 0 ----
    {
        float4 a0 = make_float4(0.f, 0.f, 0.f, 0.f), a1 = a0;
        if (r0 < M) a0 = *(const float4*)(A + (size_t)r0 * K + aCol);
        if (r1 < M) a1 = *(const float4*)(A + (size_t)r1 * K + aCol);
        if (reluA) {
            a0.x = fmaxf(a0.x, 0.f); a0.y = fmaxf(a0.y, 0.f); a0.z = fmaxf(a0.z, 0.f); a0.w = fmaxf(a0.w, 0.f);
            a1.x = fmaxf(a1.x, 0.f); a1.y = fmaxf(a1.y, 0.f); a1.z = fmaxf(a1.z, 0.f); a1.w = fmaxf(a1.w, 0.f);
        }
        As[0][aCol + 0][aRow] = a0.x; As[0][aCol + 1][aRow] = a0.y;
        As[0][aCol + 2][aRow] = a0.z; As[0][aCol + 3][aRow] = a0.w;
        As[0][aCol + 0][aRow + 64] = a1.x; As[0][aCol + 1][aRow + 64] = a1.y;
        As[0][aCol + 2][aRow + 64] = a1.z; As[0][aCol + 3][aRow + 64] = a1.w;

        *(float4*)&Bs[0][bRow][bCol]     = *(const float4*)(B + (size_t)bRow * Nc + colBase + bCol);
        *(float4*)&Bs[0][bRow + 8][bCol] = *(const float4*)(B + (size_t)(bRow + 8) * Nc + colBase + bCol);
    }
    __syncthreads();

    int buf = 0;
    for (int k0 = 0; k0 < K; k0 += BK) {
        const int kn = k0 + BK;
        const bool has = kn < K;
        float4 a0, a1, b0, b1;
        if (has) {
            a0 = make_float4(0.f, 0.f, 0.f, 0.f); a1 = a0;
            if (r0 < M) a0 = *(const float4*)(A + (size_t)r0 * K + kn + aCol);
            if (r1 < M) a1 = *(const float4*)(A + (size_t)r1 * K + kn + aCol);
            if (reluA) {
                a0.x = fmaxf(a0.x, 0.f); a0.y = fmaxf(a0.y, 0.f); a0.z = fmaxf(a0.z, 0.f); a0.w = fmaxf(a0.w, 0.f);
                a1.x = fmaxf(a1.x, 0.f); a1.y = fmaxf(a1.y, 0.f); a1.z = fmaxf(a1.z, 0.f); a1.w = fmaxf(a1.w, 0.f);
            }
            b0 = *(const float4*)(B + (size_t)(kn + bRow) * Nc + colBase + bCol);
            b1 = *(const float4*)(B + (size_t)(kn + bRow + 8) * Nc + colBase + bCol);
        }

#pragma unroll
        for (int kk = 0; kk < BK; kk++) {
            float a[8], b[8];
            *(float4*)&a[0] = *(const float4*)&As[buf][kk][ty * 8];
            *(float4*)&a[4] = *(const float4*)&As[buf][kk][ty * 8 + 4];
            *(float4*)&b[0] = *(const float4*)&Bs[buf][kk][tx * 8];
            *(float4*)&b[4] = *(const float4*)&Bs[buf][kk][tx * 8 + 4];
#pragma unroll
            for (int i = 0; i < 8; i++)
#pragma unroll
                for (int j = 0; j < 8; j++) acc[i][j] += a[i] * b[j];
        }

        if (has) {
            const int nb = buf ^ 1;
            As[nb][aCol + 0][aRow] = a0.x; As[nb][aCol + 1][aRow] = a0.y;
            As[nb][aCol + 2][aRow] = a0.z; As[nb][aCol + 3][aRow] = a0.w;
            As[nb][aCol + 0][aRow + 64] = a1.x; As[nb][aCol + 1][aRow + 64] = a1.y;
            As[nb][aCol + 2][aRow + 64] = a1.z; As[nb][aCol + 3][aRow + 64] = a1.w;
            *(float4*)&Bs[nb][bRow][bCol]     = b0;
            *(float4*)&Bs[nb][bRow + 8][bCol] = b1;
        }
        __syncthreads();
        buf ^= 1;
    }

    // ---- epilogue ----
    float bv[8];
    if (bias) {
#pragma unroll
        for (int j = 0; j < 8; j++) bv[j] = bias[colBase + tx * 8 + j];
    } else {
#pragma unroll
        for (int j = 0; j < 8; j++) bv[j] = 0.f;
    }
    const bool reluO = (flags & 1) != 0;
#pragma unroll
    for (int i = 0; i < 8; i++) {
        int r = rowBase + ty * 8 + i;
        if (r >= M) continue;
        float* crow = C + (size_t)r * Nc + colBase + tx * 8;
        float4 v0, v1;
        v0.x = acc[i][0] + bv[0]; v0.y = acc[i][1] + bv[1];
        v0.z = acc[i][2] + bv[2]; v0.w = acc[i][3] + bv[3];
        v1.x = acc[i][4] + bv[4]; v1.y = acc[i][5] + bv[5];
        v1.z = acc[i][6] + bv[6]; v1.w = acc[i][7] + bv[7];
        if (reluO) {
            v0.x = fmaxf(v0.x, 0.f); v0.y = fmaxf(v0.y, 0.f); v0.z = fmaxf(v0.z, 0.f); v0.w = fmaxf(v0.w, 0.f);
            v1.x = fmaxf(v1.x, 0.f); v1.y = fmaxf(v1.y, 0.f); v1.z = fmaxf(v1.z, 0.f); v1.w = fmaxf(v1.w, 0.f);
        }
        *(float4*)crow = v0;
        *(float4*)(crow + 4) = v1;
    }
}

// ---------------- link head ----------------
// H0[e,j] = relu(U[a]+V[b]+lb0[j]); first ET rows fwd (a=s,b=d), next ET rev (a=d,b=s)
// UV layout: [N,256], U = cols 0..127, V = cols 128..255
__global__ void build_h0_kernel(const float* __restrict__ UV,
                                const float* __restrict__ lb0, const int* __restrict__ eit,
                                float* __restrict__ Hout)
{
    size_t idx = (size_t)blockIdx.x * blockDim.x + threadIdx.x;
    if (idx >= (size_t)2 * ET_EDGES * HLDIM) return;
    int e = (int)(idx >> 7);
    int j = (int)(idx & 127);
    int a, b;
    if (e < ET_EDGES) { a = eit[e]; b = eit[ET_EDGES + e]; }
    else              { int e2 = e - ET_EDGES; a = eit[ET_EDGES + e2]; b = eit[e2]; }
    float v = UV[(size_t)a * 256 + j] + UV[(size_t)b * 256 + 128 + j] + lb0[j];
    Hout[idx] = fmaxf(v, 0.f);
}

// final layer: T[m,0..3] = H[m,:] @ lw4 + lb4 ; warp per row
__global__ __launch_bounds__(256) void gemm_out_kernel(
    const float* __restrict__ Hm, const float* __restrict__ lw4,
    const float* __restrict__ lb4, float* __restrict__ T, int M)
{
    int w = (blockIdx.x * blockDim.x + threadIdx.x) >> 5;
    int lane = threadIdx.x & 31;
    if (w >= M) return;
    float h0 = Hm[(size_t)w * HLDIM + lane];
    float h1 = Hm[(size_t)w * HLDIM + 32 + lane];
    float h2 = Hm[(size_t)w * HLDIM + 64 + lane];
    float h3 = Hm[(size_t)w * HLDIM + 96 + lane];
    float acc[4];
#pragma unroll
    for (int c = 0; c < 4; c++) {
        acc[c] = h0 * __ldg(&lw4[lane * 4 + c])
               + h1 * __ldg(&lw4[(lane + 32) * 4 + c])
               + h2 * __ldg(&lw4[(lane + 64) * 4 + c])
               + h3 * __ldg(&lw4[(lane + 96) * 4 + c]);
    }
#pragma unroll
    for (int off = 16; off > 0; off >>= 1)
#pragma unroll
        for (int c = 0; c < 4; c++) acc[c] += __shfl_down_sync(0xffffffffu, acc[c], off);
    if (lane == 0) {
#pragma unroll
        for (int c = 0; c < 4; c++) T[(size_t)w * 4 + c] = acc[c] + lb4[c];
    }
}

// out[e,c] = 0.5*(T[e,c] + T[ET+e, perm[c]]), perm = [0,2,1,3]
__global__ void combine_kernel(const float* __restrict__ T, float* __restrict__ out) {
    int idx = blockIdx.x * blockDim.x + threadIdx.x;
    if (idx >= ET_EDGES * 4) return;
    int e = idx >> 2, c = idx & 3;
    int pc = (c == 1) ? 2 : (c == 2) ? 1 : c;
    out[idx] = 0.5f * (T[(size_t)e * 4 + c] + T[(size_t)(ET_EDGES + e) * 4 + pc]);
}

// ---------------- host orchestration ----------------
static inline int cdiv(size_t a, int b) { return (int)((a + b - 1) / b); }

extern "C" void kernel_launch(void* const* d_in, const int* in_sizes, int n_in,
                              void* d_out, int out_size)
{
    const float* x    = (const float*)d_in[0];
    const int*   ei   = (const int*)  d_in[1];
    const float* ea   = (const float*)d_in[2];
    const int*   eit  = (const int*)  d_in[3];
    const float* W0   = (const float*)d_in[4];
    const float* b0   = (const float*)d_in[5];
    const float* W1   = (const float*)d_in[6];
    const float* b1   = (const float*)d_in[7];
    const float* W2   = (const float*)d_in[8];
    const float* b2   = (const float*)d_in[9];
    const float* W3   = (const float*)d_in[10];
    const float* b3   = (const float*)d_in[11];
    const float* ew1  = (const float*)d_in[12];
    const float* eb1  = (const float*)d_in[13];
    const float* ew2  = (const float*)d_in[14];
    const float* eb2  = (const float*)d_in[15];
    const float* ew3  = (const float*)d_in[16];
    const float* eb3  = (const float*)d_in[17];
    const float* lw0  = (const float*)d_in[18];
    const float* lb0  = (const float*)d_in[19];
    const float* lwh  = (const float*)d_in[20];
    const float* lbh  = (const float*)d_in[21];
    const float* lw4  = (const float*)d_in[22];
    const float* lb4  = (const float*)d_in[23];
    float* out = (float*)d_out;

    float *ew, *dis, *W0r, *W2r, *W3r, *Wuv, *hw, *hw128, *x1, *x2b, *x3, *x4, *UV, *Ha, *Hb, *T;
    cudaGetSymbolAddress((void**)&ew,    g_ew);
    cudaGetSymbolAddress((void**)&dis,   g_dis);
    cudaGetSymbolAddress((void**)&W0r,   g_W0r);
    cudaGetSymbolAddress((void**)&W2r,   g_W2r);
    cudaGetSymbolAddress((void**)&W3r,   g_W3r);
    cudaGetSymbolAddress((void**)&Wuv,   g_Wuv);
    cudaGetSymbolAddress((void**)&hw,    g_hw);
    cudaGetSymbolAddress((void**)&hw128, g_hw128);
    cudaGetSymbolAddress((void**)&x1,    g_x1);
    cudaGetSymbolAddress((void**)&x2b,   g_xb2);
    cudaGetSymbolAddress((void**)&x3,    g_x3);
    cudaGetSymbolAddress((void**)&x4,    g_x4);
    cudaGetSymbolAddress((void**)&UV,    g_UV);
    cudaGetSymbolAddress((void**)&Ha,    g_Ha);
    cudaGetSymbolAddress((void**)&Hb,    g_Hb);
    cudaGetSymbolAddress((void**)&T,     g_T);

    const int TB = 256;
    const size_t NW = (size_t)N_NODES * HC;
    const size_t NN = (size_t)N_NODES * HDIM;

    // 1) edge-weight MLP
    edge_mlp_kernel<<<cdiv(E_EDGES, TB), TB>>>(ea, ew1, eb1, ew2, eb2, ew3, eb3, ew, E_EDGES);

    // 2) degrees -> dis = rsqrt(deg) for 8 channels
    deg_init_kernel<<<cdiv(8 * N_NODES, TB), TB>>>(dis, 8 * N_NODES);
    deg_accum_kernel<<<cdiv(E_EDGES, TB), TB>>>(ei, ea, ew, dis, E_EDGES, N_NODES);
    deg_rsqrt_kernel<<<cdiv(8 * N_NODES, TB), TB>>>(dis, 8 * N_NODES);

    // 3) pack weights
    pack_w_kernel<<<cdiv(DIN * HC, TB), TB>>>(W0, W0r, DIN);
    pack_w_kernel<<<cdiv(HDIM * HC, TB), TB>>>(W2, W2r, HDIM);
    pack_w_kernel<<<cdiv(HC * HC, TB), TB>>>(W3, W3r, HC);
    pack_uv_kernel<<<cdiv(HC * 256, TB), TB>>>(lw0, Wuv);

    // ---- layer 1 ----
    gemm_k8_kernel<<<cdiv(NW, TB), TB>>>(x, W0r, hw);
    init_self_kernel<<<cdiv(NW, TB), TB>>>(hw, b0, dis, x1, HC);
    scatter7_kernel<<<cdiv((size_t)E_EDGES * 32, TB), TB>>>(hw, x1, ei, ea, dis, E_EDGES);
    // relu fused into layer-2 GEMM A-load

    // ---- layer 2 (ew norm) ----
    {
        dim3 g(HDIM / BN, cdiv(N_NODES, BM));
        sgemm_kernel<<<g, 256>>>(x1, W1, hw128, N_NODES, HC, HDIM, nullptr, 2);
    }
    init_self_kernel<<<cdiv(NN, TB), TB>>>(hw128, b1, dis + NEA * N_NODES, x2b, HDIM);
    scatter1_kernel<<<cdiv((size_t)E_EDGES * 32, TB), TB>>>(hw128, x2b, ei, ew, dis + NEA * N_NODES, E_EDGES);

    // ---- layer 3 ----
    {
        dim3 g(HC / BN, cdiv(N_NODES, BM));
        sgemm_kernel<<<g, 256>>>(x2b, W2r, hw, N_NODES, HDIM, HC, nullptr, 2);
    }
    init_self_kernel<<<cdiv(NW, TB), TB>>>(hw, b2, dis, x3, HC);
    scatter7_kernel<<<cdiv((size_t)E_EDGES * 32, TB), TB>>>(hw, x3, ei, ea, dis, E_EDGES);

    // ---- layer 4 ----
    {
        dim3 g(HC / BN, cdiv(N_NODES, BM));
        sgemm_kernel<<<g, 256>>>(x3, W3r, hw, N_NODES, HC, HC, nullptr, 2);
    }
    init_self_kernel<<<cdiv(NW, TB), TB>>>(hw, b3, dis, x4, HC);
    scatter7_kernel<<<cdiv((size_t)E_EDGES * 32, TB), TB>>>(hw, x4, ei, ea, dis, E_EDGES);

    // ---- link head: UV = relu(x4) @ Wuv  ([20000,896]@[896,256]) ----
    {
        dim3 g(256 / BN, cdiv(N_NODES, BM));
        sgemm_kernel<<<g, 256>>>(x4, Wuv, UV, N_NODES, HC, 256, nullptr, 2);
    }

    const int M2 = 2 * ET_EDGES;
    build_h0_kernel<<<cdiv((size_t)M2 * HLDIM, TB), TB>>>(UV, lb0, eit, Ha);

    // 3 hidden layers with bias+relu fused
    {
        dim3 g(HLDIM / BN, cdiv(M2, BM));
        sgemm_kernel<<<g, 256>>>(Ha, lwh,                 Hb, M2, HLDIM, HLDIM, lbh,       1);
        sgemm_kernel<<<g, 256>>>(Hb, lwh + 128 * 128,     Ha, M2, HLDIM, HLDIM, lbh + 128, 1);
        sgemm_kernel<<<g, 256>>>(Ha, lwh + 2 * 128 * 128, Hb, M2, HLDIM, HLDIM, lbh + 256, 1);
    }

    gemm_out_kernel<<<cdiv((size_t)M2 * 32, TB), TB>>>(Hb, lw4, lb4, T, M2);
    combine_kernel<<<cdiv(ET_EDGES * 4, TB), TB>>>(T, out);
}

// round 3
// speedup vs baseline: 1.0242x; 1.0227x over previous
#include <cuda_runtime.h>
#include <math.h>

// Problem constants (fixed by dataset)
#define N_NODES 20000
#define E_EDGES 200000
#define ET_EDGES 40000
#define DIN 8
#define HDIM 128
#define NEA 7
#define HC 896          // 7*128
#define HLDIM 128
#define OUTD 4

// ---------------- scratch (static device globals; no runtime allocation) ----------------
static __device__ float g_ew[E_EDGES];
static __device__ float g_dis[8 * N_NODES];            // 7 attr channels + 1 ew channel
static __device__ float g_W0r[DIN * HC];
static __device__ float g_W2r[HDIM * HC];
static __device__ float g_W3r[HC * HC];
static __device__ float g_Wuv[HC * 256];
static __device__ float g_hw[(size_t)N_NODES * HC];    // h@W scratch (wide)
static __device__ float g_hw128[(size_t)N_NODES * HDIM];
static __device__ float g_x1[(size_t)N_NODES * HC];
static __device__ float g_xb2[(size_t)N_NODES * HDIM];
static __device__ float g_x3[(size_t)N_NODES * HC];
static __device__ float g_x4[(size_t)N_NODES * HC];
static __device__ float g_UV[(size_t)N_NODES * 256];
static __device__ float g_Ha[(size_t)2 * ET_EDGES * HLDIM];
static __device__ float g_Hb[(size_t)2 * ET_EDGES * HLDIM];
static __device__ float g_T[(size_t)2 * ET_EDGES * OUTD];
// CSR (by destination column)
static __device__ int g_cnt[N_NODES];
static __device__ int g_cursor[N_NODES];
static __device__ int g_rowptr[N_NODES + 1];
static __device__ int g_csr_r[E_EDGES];
static __device__ int g_csr_e[E_EDGES];

// ---------------- edge-weight MLP: [E,7] -> sigmoid scalar ----------------
__global__ __launch_bounds__(256) void edge_mlp_kernel(
    const float* __restrict__ ea,
    const float* __restrict__ w1, const float* __restrict__ bb1,
    const float* __restrict__ w2, const float* __restrict__ bb2,
    const float* __restrict__ w3, const float* __restrict__ bb3,
    float* __restrict__ out, int E)
{
    __shared__ float s1[NEA * 28], sb1[28], s2[28 * 28], sb2[28], s3[28], sb3v[1];
    for (int i = threadIdx.x; i < NEA * 28; i += blockDim.x) s1[i] = w1[i];
    for (int i = threadIdx.x; i < 28; i += blockDim.x) { sb1[i] = bb1[i]; sb2[i] = bb2[i]; s3[i] = w3[i]; }
    for (int i = threadIdx.x; i < 28 * 28; i += blockDim.x) s2[i] = w2[i];
    if (threadIdx.x == 0) sb3v[0] = bb3[0];
    __syncthreads();

    int e = blockIdx.x * blockDim.x + threadIdx.x;
    if (e >= E) return;
    float a[NEA];
#pragma unroll
    for (int k = 0; k < NEA; k++) a[k] = ea[(size_t)e * NEA + k];
    float t[28];
#pragma unroll
    for (int j = 0; j < 28; j++) {
        float v = sb1[j];
#pragma unroll
        for (int k = 0; k < NEA; k++) v += a[k] * s1[k * 28 + j];
        t[j] = fmaxf(v, 0.f);
    }
    float u[28];
#pragma unroll
    for (int j = 0; j < 28; j++) {
        float v = sb2[j];
#pragma unroll
        for (int k = 0; k < 28; k++) v += t[k] * s2[k * 28 + j];
        u[j] = fmaxf(v, 0.f);
    }
    float z = sb3v[0];
#pragma unroll
    for (int k = 0; k < 28; k++) z += u[k] * s3[k];
    out[e] = 1.f / (1.f + expf(-z));
}

// ---------------- CSR build ----------------
__global__ void zero_int_kernel(int* __restrict__ p, int n) {
    int i = blockIdx.x * blockDim.x + threadIdx.x;
    if (i < n) p[i] = 0;
}

__global__ void count_kernel(const int* __restrict__ ei, int* __restrict__ cnt, int E) {
    int e = blockIdx.x * blockDim.x + threadIdx.x;
    if (e < E) atomicAdd(&cnt[ei[E + e]], 1);
}

// single-block scan over n<=20480 elements, 1024 threads
__global__ __launch_bounds__(1024) void scan_kernel(
    const int* __restrict__ cnt, int* __restrict__ rowptr, int* __restrict__ cursor, int n)
{
    __shared__ int s[1024];
    const int t = threadIdx.x;
    const int C = (n + 1023) / 1024;
    const int base = t * C;
    int local = 0;
    for (int i = 0; i < C; i++) { int idx = base + i; if (idx < n) local += cnt[idx]; }
    s[t] = local; __syncthreads();
    for (int off = 1; off < 1024; off <<= 1) {
        int v = (t >= off) ? s[t - off] : 0;
        __syncthreads();
        s[t] += v;
        __syncthreads();
    }
    int run = (t == 0) ? 0 : s[t - 1];
    if (t == 0) rowptr[0] = 0;
    for (int i = 0; i < C; i++) {
        int idx = base + i;
        if (idx < n) {
            cursor[idx] = run;
            run += cnt[idx];
            rowptr[idx + 1] = run;
        }
    }
}

__global__ void csr_fill_kernel(const int* __restrict__ ei, int* __restrict__ cursor,
                                int* __restrict__ csr_r, int* __restrict__ csr_e, int E)
{
    int e = blockIdx.x * blockDim.x + threadIdx.x;
    if (e >= E) return;
    int r = ei[e], c = ei[E + e];
    int pos = atomicAdd(&cursor[c], 1);
    csr_r[pos] = r;
    csr_e[pos] = e;
}

// ---------------- degrees via CSR: dis[i*N+v] = rsqrt(1 + sum_in ea/ew) ----------------
__global__ void deg_csr_kernel(const int* __restrict__ rowptr, const int* __restrict__ csr_e,
                               const float* __restrict__ ea, const float* __restrict__ ew,
                               float* __restrict__ dis)
{
    int idx = blockIdx.x * blockDim.x + threadIdx.x;
    if (idx >= 8 * N_NODES) return;
    int i = idx / N_NODES, v = idx % N_NODES;
    int p0 = rowptr[v], p1 = rowptr[v + 1];
    float s = 1.0f;   // self-loop weight
    if (i < NEA) {
        for (int p = p0; p < p1; p++) s += __ldg(&ea[(size_t)csr_e[p] * NEA + i]);
    } else {
        for (int p = p0; p < p1; p++) s += __ldg(&ew[csr_e[p]]);
    }
    dis[idx] = rsqrtf(s);
}

// ---------------- weight pack: [7,K,128] -> [K,896] ----------------
__global__ void pack_w_kernel(const float* __restrict__ in, float* __restrict__ out, int K) {
    int idx = blockIdx.x * blockDim.x + threadIdx.x;
    int total = K * HC;
    if (idx >= total) return;
    int k = idx / HC, c = idx % HC;
    int i = c >> 7, j = c & 127;
    out[idx] = in[((size_t)i * K + k) * HDIM + j];
}

// pack lw0 [2*HC,128] -> Wuv [HC,256]
__global__ void pack_uv_kernel(const float* __restrict__ lw0, float* __restrict__ out) {
    int idx = blockIdx.x * blockDim.x + threadIdx.x;
    if (idx >= HC * 256) return;
    int k = idx >> 8, c = idx & 255;
    out[idx] = (c < 128) ? lw0[(size_t)k * 128 + c]
                         : lw0[(size_t)(HC + k) * 128 + (c - 128)];
}

// ---------------- G0: x[N,8] @ W0r[8,896] ----------------
__global__ void gemm_k8_kernel(const float* __restrict__ x, const float* __restrict__ W,
                               float* __restrict__ out)
{
    int idx = blockIdx.x * blockDim.x + threadIdx.x;
    if (idx >= N_NODES * HC) return;
    int m = idx / HC, c = idx % HC;
    float v = 0.f;
#pragma unroll
    for (int k = 0; k < DIN; k++) v += __ldg(&x[m * DIN + k]) * W[k * HC + c];
    out[idx] = v;
}

// ---------------- CSR scatter, 7-channel wide (C=896): one warp per dest node ----------------
// out[c,:] = relu( bias + dis_c^2 * hw[c,:] + sum_in coef_e * hw[r,:] )
__global__ __launch_bounds__(256) void scatter7_csr_kernel(
    const float* __restrict__ hw, float* __restrict__ out,
    const int* __restrict__ rowptr, const int* __restrict__ csr_r, const int* __restrict__ csr_e,
    const float* __restrict__ ea, const float* __restrict__ dis,
    const float* __restrict__ bias)
{
    int c = (blockIdx.x * blockDim.x + threadIdx.x) >> 5;
    int lane = threadIdx.x & 31;
    if (c >= N_NODES) return;

    // per-channel dest norm, broadcast to all lanes
    float dci = (lane < NEA) ? __ldg(&dis[lane * N_NODES + c]) : 0.f;
    float dc[NEA];
#pragma unroll
    for (int i = 0; i < NEA; i++) dc[i] = __shfl_sync(0xffffffffu, dci, i);

    float4 acc[NEA];
    const float* srow = hw + (size_t)c * HC;
#pragma unroll
    for (int i = 0; i < NEA; i++) {
        float4 v = *(const float4*)(srow + i * HDIM + lane * 4);
        float4 b = *(const float4*)(bias + i * HDIM + lane * 4);
        float s = dc[i] * dc[i];
        acc[i].x = b.x + s * v.x; acc[i].y = b.y + s * v.y;
        acc[i].z = b.z + s * v.z; acc[i].w = b.w + s * v.w;
    }

    int p0 = __ldg(&rowptr[c]), p1 = __ldg(&rowptr[c + 1]);
    for (int p = p0; p < p1; p++) {
        int r = __ldg(&csr_r[p]);
        int e = __ldg(&csr_e[p]);
        float cof = (lane < NEA)
            ? __ldg(&dis[lane * N_NODES + r]) * __ldg(&ea[(size_t)e * NEA + lane])
            : 0.f;
        float co[NEA];
#pragma unroll
        for (int i = 0; i < NEA; i++) co[i] = __shfl_sync(0xffffffffu, cof, i) * dc[i];
        const float* rr = hw + (size_t)r * HC;
#pragma unroll
        for (int i = 0; i < NEA; i++) {
            float4 v = *(const float4*)(rr + i * HDIM + lane * 4);
            acc[i].x += co[i] * v.x; acc[i].y += co[i] * v.y;
            acc[i].z += co[i] * v.z; acc[i].w += co[i] * v.w;
        }
    }

    float* orow = out + (size_t)c * HC;
#pragma unroll
    for (int i = 0; i < NEA; i++) {
        float4 v = acc[i];
        v.x = fmaxf(v.x, 0.f); v.y = fmaxf(v.y, 0.f);
        v.z = fmaxf(v.z, 0.f); v.w = fmaxf(v.w, 0.f);
        *(float4*)(orow + i * HDIM + lane * 4) = v;
    }
}

// ---------------- CSR scatter, single channel (C=128, ew norm) ----------------
__global__ __launch_bounds__(256) void scatter1_csr_kernel(
    const float* __restrict__ hw, float* __restrict__ out,
    const int* __restrict__ rowptr, const int* __restrict__ csr_r, const int* __restrict__ csr_e,
    const float* __restrict__ ew, const float* __restrict__ dis7,   // pre-offset to channel 7
    const float* __restrict__ bias)
{
    int c = (blockIdx.x * blockDim.x + threadIdx.x) >> 5;
    int lane = threadIdx.x & 31;
    if (c >= N_NODES) return;

    float dc = __ldg(&dis7[c]);
    float4 acc;
    {
        float4 v = *(const float4*)(hw + (size_t)c * HDIM + lane * 4);
        float4 b = *(const float4*)(bias + lane * 4);
        float s = dc * dc;
        acc.x = b.x + s * v.x; acc.y = b.y + s * v.y;
        acc.z = b.z + s * v.z; acc.w = b.w + s * v.w;
    }
    int p0 = __ldg(&rowptr[c]), p1 = __ldg(&rowptr[c + 1]);
    for (int p = p0; p < p1; p++) {
        int r = __ldg(&csr_r[p]);
        int e = __ldg(&csr_e[p]);
        float co = __ldg(&dis7[r]) * dc * __ldg(&ew[e]);
        float4 v = *(const float4*)(hw + (size_t)r * HDIM + lane * 4);
        acc.x += co * v.x; acc.y += co * v.y;
        acc.z += co * v.z; acc.w += co * v.w;
    }
    acc.x = fmaxf(acc.x, 0.f); acc.y = fmaxf(acc.y, 0.f);
    acc.z = fmaxf(acc.z, 0.f); acc.w = fmaxf(acc.w, 0.f);
    *(float4*)(out + (size_t)c * HDIM + lane * 4) = acc;
}

// ---------------- SGEMM: C[M,Nc] = A[M,K] @ B[K,Nc] (+bias)(+relu) ----------------
// BM=BN=128, BK=16, 256 threads, 8x8 per thread, double-buffered smem.
#define BM 128
#define BN 128
#define BK 16
__global__ __launch_bounds__(256) void sgemm_kernel(
    const float* __restrict__ A, const float* __restrict__ B, float* __restrict__ C,
    int M, int K, int Nc, const float* __restrict__ bias, int flags)
{
    __shared__ float As[2][BK][BM];
    __shared__ float Bs[2][BK][BN];

    const int tid = threadIdx.x;
    const int rowBase = blockIdx.y * BM;
    const int colBase = blockIdx.x * BN;

    const int aRow = tid >> 2;
    const int aCol = (tid & 3) << 2;
    const int bRow = tid >> 5;
    const int bCol = (tid & 31) << 2;

    const int ty = tid >> 4;
    const int tx = tid & 15;

    float acc[8][8];
#pragma unroll
    for (int i = 0; i < 8; i++)
#pragma unroll
        for (int j = 0; j < 8; j++) acc[i][j] = 0.f;

    const int r0 = rowBase + aRow;
    const int r1 = rowBase + aRow + 64;

    {
        float4 a0 = make_float4(0.f, 0.f, 0.f, 0.f), a1 = a0;
        if (r0 < M) a0 = *(const float4*)(A + (size_t)r0 * K + aCol);
        if (r1 < M) a1 = *(const float4*)(A + (size_t)r1 * K + aCol);
        As[0][aCol + 0][aRow] = a0.x; As[0][aCol + 1][aRow] = a0.y;
        As[0][aCol + 2][aRow] = a0.z; As[0][aCol + 3][aRow] = a0.w;
        As[0][aCol + 0][aRow + 64] = a1.x; As[0][aCol + 1][aRow + 64] = a1.y;
        As[0][aCol + 2][aRow + 64] = a1.z; As[0][aCol + 3][aRow + 64] = a1.w;

        *(float4*)&Bs[0][bRow][bCol]     = *(const float4*)(B + (size_t)bRow * Nc + colBase + bCol);
        *(float4*)&Bs[0][bRow + 8][bCol] = *(const float4*)(B + (size_t)(bRow + 8) * Nc + colBase + bCol);
    }
    __syncthreads();

    int buf = 0;
    for (int k0 = 0; k0 < K; k0 += BK) {
        const int kn = k0 + BK;
        const bool has = kn < K;
        float4 a0, a1, b0, b1;
        if (has) {
            a0 = make_float4(0.f, 0.f, 0.f, 0.f); a1 = a0;
            if (r0 < M) a0 = *(const float4*)(A + (size_t)r0 * K + kn + aCol);
            if (r1 < M) a1 = *(const float4*)(A + (size_t)r1 * K + kn + aCol);
            b0 = *(const float4*)(B + (size_t)(kn + bRow) * Nc + colBase + bCol);
            b1 = *(const float4*)(B + (size_t)(kn + bRow + 8) * Nc + colBase + bCol);
        }

#pragma unroll
        for (int kk = 0; kk < BK; kk++) {
            float a[8], b[8];
            *(float4*)&a[0] = *(const float4*)&As[buf][kk][ty * 8];
            *(float4*)&a[4] = *(const float4*)&As[buf][kk][ty * 8 + 4];
            *(float4*)&b[0] = *(const float4*)&Bs[buf][kk][tx * 8];
            *(float4*)&b[4] = *(const float4*)&Bs[buf][kk][tx * 8 + 4];
#pragma unroll
            for (int i = 0; i < 8; i++)
#pragma unroll
                for (int j = 0; j < 8; j++) acc[i][j] += a[i] * b[j];
        }

        if (has) {
            const int nb = buf ^ 1;
            As[nb][aCol + 0][aRow] = a0.x; As[nb][aCol + 1][aRow] = a0.y;
            As[nb][aCol + 2][aRow] = a0.z; As[nb][aCol + 3][aRow] = a0.w;
            As[nb][aCol + 0][aRow + 64] = a1.x; As[nb][aCol + 1][aRow + 64] = a1.y;
            As[nb][aCol + 2][aRow + 64] = a1.z; As[nb][aCol + 3][aRow + 64] = a1.w;
            *(float4*)&Bs[nb][bRow][bCol]     = b0;
            *(float4*)&Bs[nb][bRow + 8][bCol] = b1;
        }
        __syncthreads();
        buf ^= 1;
    }

    float bv[8];
    if (bias) {
#pragma unroll
        for (int j = 0; j < 8; j++) bv[j] = bias[colBase + tx * 8 + j];
    } else {
#pragma unroll
        for (int j = 0; j < 8; j++) bv[j] = 0.f;
    }
    const bool reluO = (flags & 1) != 0;
#pragma unroll
    for (int i = 0; i < 8; i++) {
        int r = rowBase + ty * 8 + i;
        if (r >= M) continue;
        float* crow = C + (size_t)r * Nc + colBase + tx * 8;
        float4 v0, v1;
        v0.x = acc[i][0] + bv[0]; v0.y = acc[i][1] + bv[1];
        v0.z = acc[i][2] + bv[2]; v0.w = acc[i][3] + bv[3];
        v1.x = acc[i][4] + bv[4]; v1.y = acc[i][5] + bv[5];
        v1.z = acc[i][6] + bv[6]; v1.w = acc[i][7] + bv[7];
        if (reluO) {
            v0.x = fmaxf(v0.x, 0.f); v0.y = fmaxf(v0.y, 0.f); v0.z = fmaxf(v0.z, 0.f); v0.w = fmaxf(v0.w, 0.f);
            v1.x = fmaxf(v1.x, 0.f); v1.y = fmaxf(v1.y, 0.f); v1.z = fmaxf(v1.z, 0.f); v1.w = fmaxf(v1.w, 0.f);
        }
        *(float4*)crow = v0;
        *(float4*)(crow + 4) = v1;
    }
}

// ---------------- link head ----------------
__global__ void build_h0_kernel(const float* __restrict__ UV,
                                const float* __restrict__ lb0, const int* __restrict__ eit,
                                float* __restrict__ Hout)
{
    size_t idx = (size_t)blockIdx.x * blockDim.x + threadIdx.x;
    if (idx >= (size_t)2 * ET_EDGES * HLDIM) return;
    int e = (int)(idx >> 7);
    int j = (int)(idx & 127);
    int a, b;
    if (e < ET_EDGES) { a = eit[e]; b = eit[ET_EDGES + e]; }
    else              { int e2 = e - ET_EDGES; a = eit[ET_EDGES + e2]; b = eit[e2]; }
    float v = UV[(size_t)a * 256 + j] + UV[(size_t)b * 256 + 128 + j] + lb0[j];
    Hout[idx] = fmaxf(v, 0.f);
}

__global__ __launch_bounds__(256) void gemm_out_kernel(
    const float* __restrict__ Hm, const float* __restrict__ lw4,
    const float* __restrict__ lb4, float* __restrict__ T, int M)
{
    int w = (blockIdx.x * blockDim.x + threadIdx.x) >> 5;
    int lane = threadIdx.x & 31;
    if (w >= M) return;
    float h0 = Hm[(size_t)w * HLDIM + lane];
    float h1 = Hm[(size_t)w * HLDIM + 32 + lane];
    float h2 = Hm[(size_t)w * HLDIM + 64 + lane];
    float h3 = Hm[(size_t)w * HLDIM + 96 + lane];
    float acc[4];
#pragma unroll
    for (int c = 0; c < 4; c++) {
        acc[c] = h0 * __ldg(&lw4[lane * 4 + c])
               + h1 * __ldg(&lw4[(lane + 32) * 4 + c])
               + h2 * __ldg(&lw4[(lane + 64) * 4 + c])
               + h3 * __ldg(&lw4[(lane + 96) * 4 + c]);
    }
#pragma unroll
    for (int off = 16; off > 0; off >>= 1)
#pragma unroll
        for (int c = 0; c < 4; c++) acc[c] += __shfl_down_sync(0xffffffffu, acc[c], off);
    if (lane == 0) {
#pragma unroll
        for (int c = 0; c < 4; c++) T[(size_t)w * 4 + c] = acc[c] + lb4[c];
    }
}

__global__ void combine_kernel(const float* __restrict__ T, float* __restrict__ out) {
    int idx = blockIdx.x * blockDim.x + threadIdx.x;
    if (idx >= ET_EDGES * 4) return;
    int e = idx >> 2, c = idx & 3;
    int pc = (c == 1) ? 2 : (c == 2) ? 1 : c;
    out[idx] = 0.5f * (T[(size_t)e * 4 + c] + T[(size_t)(ET_EDGES + e) * 4 + pc]);
}

// ---------------- host orchestration ----------------
static inline int cdiv(size_t a, int b) { return (int)((a + b - 1) / b); }

extern "C" void kernel_launch(void* const* d_in, const int* in_sizes, int n_in,
                              void* d_out, int out_size)
{
    const float* x    = (const float*)d_in[0];
    const int*   ei   = (const int*)  d_in[1];
    const float* ea   = (const float*)d_in[2];
    const int*   eit  = (const int*)  d_in[3];
    const float* W0   = (const float*)d_in[4];
    const float* b0   = (const float*)d_in[5];
    const float* W1   = (const float*)d_in[6];
    const float* b1   = (const float*)d_in[7];
    const float* W2   = (const float*)d_in[8];
    const float* b2   = (const float*)d_in[9];
    const float* W3   = (const float*)d_in[10];
    const float* b3   = (const float*)d_in[11];
    const float* ew1  = (const float*)d_in[12];
    const float* eb1  = (const float*)d_in[13];
    const float* ew2  = (const float*)d_in[14];
    const float* eb2  = (const float*)d_in[15];
    const float* ew3  = (const float*)d_in[16];
    const float* eb3  = (const float*)d_in[17];
    const float* lw0  = (const float*)d_in[18];
    const float* lb0  = (const float*)d_in[19];
    const float* lwh  = (const float*)d_in[20];
    const float* lbh  = (const float*)d_in[21];
    const float* lw4  = (const float*)d_in[22];
    const float* lb4  = (const float*)d_in[23];
    float* out = (float*)d_out;

    float *ew, *dis, *W0r, *W2r, *W3r, *Wuv, *hw, *hw128, *x1, *x2b, *x3, *x4, *UV, *Ha, *Hb, *T;
    int *cnt, *cursor, *rowptr, *csr_r, *csr_e;
    cudaGetSymbolAddress((void**)&ew,    g_ew);
    cudaGetSymbolAddress((void**)&dis,   g_dis);
    cudaGetSymbolAddress((void**)&W0r,   g_W0r);
    cudaGetSymbolAddress((void**)&W2r,   g_W2r);
    cudaGetSymbolAddress((void**)&W3r,   g_W3r);
    cudaGetSymbolAddress((void**)&Wuv,   g_Wuv);
    cudaGetSymbolAddress((void**)&hw,    g_hw);
    cudaGetSymbolAddress((void**)&hw128, g_hw128);
    cudaGetSymbolAddress((void**)&x1,    g_x1);
    cudaGetSymbolAddress((void**)&x2b,   g_xb2);
    cudaGetSymbolAddress((void**)&x3,    g_x3);
    cudaGetSymbolAddress((void**)&x4,    g_x4);
    cudaGetSymbolAddress((void**)&UV,    g_UV);
    cudaGetSymbolAddress((void**)&Ha,    g_Ha);
    cudaGetSymbolAddress((void**)&Hb,    g_Hb);
    cudaGetSymbolAddress((void**)&T,     g_T);
    cudaGetSymbolAddress((void**)&cnt,   g_cnt);
    cudaGetSymbolAddress((void**)&cursor,g_cursor);
    cudaGetSymbolAddress((void**)&rowptr,g_rowptr);
    cudaGetSymbolAddress((void**)&csr_r, g_csr_r);
    cudaGetSymbolAddress((void**)&csr_e, g_csr_e);

    const int TB = 256;
    const size_t NW = (size_t)N_NODES * HC;

    // 1) edge-weight MLP
    edge_mlp_kernel<<<cdiv(E_EDGES, TB), TB>>>(ea, ew1, eb1, ew2, eb2, ew3, eb3, ew, E_EDGES);

    // 2) CSR build (by destination)
    zero_int_kernel<<<cdiv(N_NODES, TB), TB>>>(cnt, N_NODES);
    count_kernel<<<cdiv(E_EDGES, TB), TB>>>(ei, cnt, E_EDGES);
    scan_kernel<<<1, 1024>>>(cnt, rowptr, cursor, N_NODES);
    csr_fill_kernel<<<cdiv(E_EDGES, TB), TB>>>(ei, cursor, csr_r, csr_e, E_EDGES);

    // 3) degrees (fused rsqrt) — needs ew from edge_mlp
    deg_csr_kernel<<<cdiv(8 * N_NODES, TB), TB>>>(rowptr, csr_e, ea, ew, dis);

    // 4) pack weights
    pack_w_kernel<<<cdiv(DIN * HC, TB), TB>>>(W0, W0r, DIN);
    pack_w_kernel<<<cdiv(HDIM * HC, TB), TB>>>(W2, W2r, HDIM);
    pack_w_kernel<<<cdiv(HC * HC, TB), TB>>>(W3, W3r, HC);
    pack_uv_kernel<<<cdiv(HC * 256, TB), TB>>>(lw0, Wuv);

    const int SCAT_GRID = cdiv((size_t)N_NODES * 32, TB);

    // ---- layer 1 ----
    gemm_k8_kernel<<<cdiv(NW, TB), TB>>>(x, W0r, hw);
    scatter7_csr_kernel<<<SCAT_GRID, TB>>>(hw, x1, rowptr, csr_r, csr_e, ea, dis, b0);

    // ---- layer 2 (ew norm) ----
    {
        dim3 g(HDIM / BN, cdiv(N_NODES, BM));
        sgemm_kernel<<<g, 256>>>(x1, W1, hw128, N_NODES, HC, HDIM, nullptr, 0);
    }
    scatter1_csr_kernel<<<SCAT_GRID, TB>>>(hw128, x2b, rowptr, csr_r, csr_e, ew,
                                           dis + NEA * N_NODES, b1);

    // ---- layer 3 ----
    {
        dim3 g(HC / BN, cdiv(N_NODES, BM));
        sgemm_kernel<<<g, 256>>>(x2b, W2r, hw, N_NODES, HDIM, HC, nullptr, 0);
    }
    scatter7_csr_kernel<<<SCAT_GRID, TB>>>(hw, x3, rowptr, csr_r, csr_e, ea, dis, b2);

    // ---- layer 4 ----
    {
        dim3 g(HC / BN, cdiv(N_NODES, BM));
        sgemm_kernel<<<g, 256>>>(x3, W3r, hw, N_NODES, HC, HC, nullptr, 0);
    }
    scatter7_csr_kernel<<<SCAT_GRID, TB>>>(hw, x4, rowptr, csr_r, csr_e, ea, dis, b3);

    // ---- link head: UV = x4 @ Wuv  ([20000,896]@[896,256]) ----
    {
        dim3 g(256 / BN, cdiv(N_NODES, BM));
        sgemm_kernel<<<g, 256>>>(x4, Wuv, UV, N_NODES, HC, 256, nullptr, 0);
    }

    const int M2 = 2 * ET_EDGES;
    build_h0_kernel<<<cdiv((size_t)M2 * HLDIM, TB), TB>>>(UV, lb0, eit, Ha);

    {
        dim3 g(HLDIM / BN, cdiv(M2, BM));
        sgemm_kernel<<<g, 256>>>(Ha, lwh,                 Hb, M2, HLDIM, HLDIM, lbh,       1);
        sgemm_kernel<<<g, 256>>>(Hb, lwh + 128 * 128,     Ha, M2, HLDIM, HLDIM, lbh + 128, 1);
        sgemm_kernel<<<g, 256>>>(Ha, lwh + 2 * 128 * 128, Hb, M2, HLDIM, HLDIM, lbh + 256, 1);
    }

    gemm_out_kernel<<<cdiv((size_t)M2 * 32, TB), TB>>>(Hb, lw4, lb4, T, M2);
    combine_kernel<<<cdiv(ET_EDGES * 4, TB), TB>>>(T, out);
}

// round 4
// speedup vs baseline: 1.1914x; 1.1633x over previous
#include <cuda_runtime.h>
#include <math.h>

// Problem constants (fixed by dataset)
#define N_NODES 20000
#define E_EDGES 200000
#define ET_EDGES 40000
#define DIN 8
#define HDIM 128
#define NEA 7
#define HC 896          // 7*128
#define HLDIM 128
#define OUTD 4

typedef unsigned long long u64;

// ---------------- scratch (static device globals; no runtime allocation) ----------------
static __device__ float g_ew[E_EDGES];
static __device__ float g_dis[8 * N_NODES];
static __device__ float g_W0r[DIN * HC];
static __device__ float g_W2r[HDIM * HC];
static __device__ float g_W3r[HC * HC];
static __device__ float g_Wuv[HC * 256];
static __device__ float g_hw[(size_t)N_NODES * HC];
static __device__ float g_hw128[(size_t)N_NODES * HDIM];
static __device__ float g_x1[(size_t)N_NODES * HC];
static __device__ float g_xb2[(size_t)N_NODES * HDIM];
static __device__ float g_x3[(size_t)N_NODES * HC];
static __device__ float g_x4[(size_t)N_NODES * HC];
static __device__ float g_UV[(size_t)N_NODES * 256];
static __device__ float g_Ha[(size_t)2 * ET_EDGES * HLDIM];
static __device__ float g_Hb[(size_t)2 * ET_EDGES * HLDIM];
static __device__ float g_T[(size_t)2 * ET_EDGES * OUTD];
// CSR (by destination column)
static __device__ int g_cnt[N_NODES];
static __device__ int g_cursor[N_NODES];
static __device__ int g_rowptr[N_NODES + 1];
static __device__ int g_csr_r[E_EDGES];
static __device__ int g_csr_e[E_EDGES];

// ---------------- packed fp32x2 helpers (sm_100+) ----------------
__device__ __forceinline__ u64 dup_f32(float x) {
    u64 r;
    asm("mov.b64 %0, {%1, %1};" : "=l"(r) : "f"(x));
    return r;
}
__device__ __forceinline__ void ffma2(u64& acc, u64 a, u64 b) {
    asm("fma.rn.f32x2 %0, %1, %2, %0;" : "+l"(acc) : "l"(a), "l"(b));
}
__device__ __forceinline__ float2 unpack_f32x2(u64 v) {
    float lo, hi;
    asm("mov.b64 {%0, %1}, %2;" : "=f"(lo), "=f"(hi) : "l"(v));
    return make_float2(lo, hi);
}

// ---------------- edge-weight MLP: [E,7] -> sigmoid scalar ----------------
__global__ __launch_bounds__(256) void edge_mlp_kernel(
    const float* __restrict__ ea,
    const float* __restrict__ w1, const float* __restrict__ bb1,
    const float* __restrict__ w2, const float* __restrict__ bb2,
    const float* __restrict__ w3, const float* __restrict__ bb3,
    float* __restrict__ out, int E)
{
    __shared__ float s1[NEA * 28], sb1[28], s2[28 * 28], sb2[28], s3[28], sb3v[1];
    for (int i = threadIdx.x; i < NEA * 28; i += blockDim.x) s1[i] = w1[i];
    for (int i = threadIdx.x; i < 28; i += blockDim.x) { sb1[i] = bb1[i]; sb2[i] = bb2[i]; s3[i] = w3[i]; }
    for (int i = threadIdx.x; i < 28 * 28; i += blockDim.x) s2[i] = w2[i];
    if (threadIdx.x == 0) sb3v[0] = bb3[0];
    __syncthreads();

    int e = blockIdx.x * blockDim.x + threadIdx.x;
    if (e >= E) return;
    float a[NEA];
#pragma unroll
    for (int k = 0; k < NEA; k++) a[k] = ea[(size_t)e * NEA + k];
    float t[28];
#pragma unroll
    for (int j = 0; j < 28; j++) {
        float v = sb1[j];
#pragma unroll
        for (int k = 0; k < NEA; k++) v += a[k] * s1[k * 28 + j];
        t[j] = fmaxf(v, 0.f);
    }
    float u[28];
#pragma unroll
    for (int j = 0; j < 28; j++) {
        float v = sb2[j];
#pragma unroll
        for (int k = 0; k < 28; k++) v += t[k] * s2[k * 28 + j];
        u[j] = fmaxf(v, 0.f);
    }
    float z = sb3v[0];
#pragma unroll
    for (int k = 0; k < 28; k++) z += u[k] * s3[k];
    out[e] = 1.f / (1.f + expf(-z));
}

// ---------------- CSR build ----------------
__global__ void zero_int_kernel(int* __restrict__ p, int n) {
    int i = blockIdx.x * blockDim.x + threadIdx.x;
    if (i < n) p[i] = 0;
}

__global__ void count_kernel(const int* __restrict__ ei, int* __restrict__ cnt, int E) {
    int e = blockIdx.x * blockDim.x + threadIdx.x;
    if (e < E) atomicAdd(&cnt[ei[E + e]], 1);
}

// single-block scan over n<=20480 elements, 1024 threads, shuffle-based
__global__ __launch_bounds__(1024) void scan_kernel(
    const int* __restrict__ cnt, int* __restrict__ rowptr, int* __restrict__ cursor, int n)
{
    __shared__ int warpsum[32];
    const int t = threadIdx.x;
    const int lane = t & 31, wid = t >> 5;
    const int C = (n + 1023) / 1024;
    const int base = t * C;
    int local = 0;
    for (int i = 0; i < C; i++) { int idx = base + i; if (idx < n) local += cnt[idx]; }
    // inclusive scan within warp
    int sc = local;
#pragma unroll
    for (int off = 1; off < 32; off <<= 1) {
        int v = __shfl_up_sync(0xffffffffu, sc, off);
        if (lane >= off) sc += v;
    }
    if (lane == 31) warpsum[wid] = sc;
    __syncthreads();
    if (wid == 0) {
        int ws = warpsum[lane];
#pragma unroll
        for (int off = 1; off < 32; off <<= 1) {
            int v = __shfl_up_sync(0xffffffffu, ws, off);
            if (lane >= off) ws += v;
        }
        warpsum[lane] = ws;
    }
    __syncthreads();
    int prefix = (wid > 0 ? warpsum[wid - 1] : 0) + (sc - local);  // exclusive prefix for this thread
    int run = prefix;
    if (t == 0) rowptr[0] = 0;
    for (int i = 0; i < C; i++) {
        int idx = base + i;
        if (idx < n) {
            cursor[idx] = run;
            run += cnt[idx];
            rowptr[idx + 1] = run;
        }
    }
}

__global__ void csr_fill_kernel(const int* __restrict__ ei, int* __restrict__ cursor,
                                int* __restrict__ csr_r, int* __restrict__ csr_e, int E)
{
    int e = blockIdx.x * blockDim.x + threadIdx.x;
    if (e >= E) return;
    int r = ei[e], c = ei[E + e];
    int pos = atomicAdd(&cursor[c], 1);
    csr_r[pos] = r;
    csr_e[pos] = e;
}

// ---------------- degrees via CSR: dis[i*N+v] = rsqrt(1 + sum_in ea/ew) ----------------
__global__ void deg_csr_kernel(const int* __restrict__ rowptr, const int* __restrict__ csr_e,
                               const float* __restrict__ ea, const float* __restrict__ ew,
                               float* __restrict__ dis)
{
    int idx = blockIdx.x * blockDim.x + threadIdx.x;
    if (idx >= 8 * N_NODES) return;
    int i = idx / N_NODES, v = idx % N_NODES;
    int p0 = rowptr[v], p1 = rowptr[v + 1];
    float s = 1.0f;
    if (i < NEA) {
        for (int p = p0; p < p1; p++) s += __ldg(&ea[(size_t)csr_e[p] * NEA + i]);
    } else {
        for (int p = p0; p < p1; p++) s += __ldg(&ew[csr_e[p]]);
    }
    dis[idx] = rsqrtf(s);
}

// ---------------- weight pack: [7,K,128] -> [K,896] ----------------
__global__ void pack_w_kernel(const float* __restrict__ in, float* __restrict__ out, int K) {
    int idx = blockIdx.x * blockDim.x + threadIdx.x;
    int total = K * HC;
    if (idx >= total) return;
    int k = idx / HC, c = idx % HC;
    int i = c >> 7, j = c & 127;
    out[idx] = in[((size_t)i * K + k) * HDIM + j];
}

// pack lw0 [2*HC,128] -> Wuv [HC,256]
__global__ void pack_uv_kernel(const float* __restrict__ lw0, float* __restrict__ out) {
    int idx = blockIdx.x * blockDim.x + threadIdx.x;
    if (idx >= HC * 256) return;
    int k = idx >> 8, c = idx & 255;
    out[idx] = (c < 128) ? lw0[(size_t)k * 128 + c]
                         : lw0[(size_t)(HC + k) * 128 + (c - 128)];
}

// ---------------- G0: x[N,8] @ W0r[8,896] ----------------
__global__ void gemm_k8_kernel(const float* __restrict__ x, const float* __restrict__ W,
                               float* __restrict__ out)
{
    int idx = blockIdx.x * blockDim.x + threadIdx.x;
    if (idx >= N_NODES * HC) return;
    int m = idx / HC, c = idx % HC;
    float v = 0.f;
#pragma unroll
    for (int k = 0; k < DIN; k++) v += __ldg(&x[m * DIN + k]) * W[k * HC + c];
    out[idx] = v;
}

// ---------------- CSR scatter, 7-channel wide (C=896) ----------------
__global__ __launch_bounds__(256) void scatter7_csr_kernel(
    const float* __restrict__ hw, float* __restrict__ out,
    const int* __restrict__ rowptr, const int* __restrict__ csr_r, const int* __restrict__ csr_e,
    const float* __restrict__ ea, const float* __restrict__ dis,
    const float* __restrict__ bias)
{
    int c = (blockIdx.x * blockDim.x + threadIdx.x) >> 5;
    int lane = threadIdx.x & 31;
    if (c >= N_NODES) return;

    float dci = (lane < NEA) ? __ldg(&dis[lane * N_NODES + c]) : 0.f;
    float dc[NEA];
#pragma unroll
    for (int i = 0; i < NEA; i++) dc[i] = __shfl_sync(0xffffffffu, dci, i);

    float4 acc[NEA];
    const float* srow = hw + (size_t)c * HC;
#pragma unroll
    for (int i = 0; i < NEA; i++) {
        float4 v = *(const float4*)(srow + i * HDIM + lane * 4);
        float4 b = *(const float4*)(bias + i * HDIM + lane * 4);
        float s = dc[i] * dc[i];
        acc[i].x = b.x + s * v.x; acc[i].y = b.y + s * v.y;
        acc[i].z = b.z + s * v.z; acc[i].w = b.w + s * v.w;
    }

    int p0 = __ldg(&rowptr[c]), p1 = __ldg(&rowptr[c + 1]);
    for (int p = p0; p < p1; p++) {
        int r = __ldg(&csr_r[p]);
        int e = __ldg(&csr_e[p]);
        float cof = (lane < NEA)
            ? __ldg(&dis[lane * N_NODES + r]) * __ldg(&ea[(size_t)e * NEA + lane])
            : 0.f;
        float co[NEA];
#pragma unroll
        for (int i = 0; i < NEA; i++) co[i] = __shfl_sync(0xffffffffu, cof, i) * dc[i];
        const float* rr = hw + (size_t)r * HC;
#pragma unroll
        for (int i = 0; i < NEA; i++) {
            float4 v = *(const float4*)(rr + i * HDIM + lane * 4);
            acc[i].x += co[i] * v.x; acc[i].y += co[i] * v.y;
            acc[i].z += co[i] * v.z; acc[i].w += co[i] * v.w;
        }
    }

    float* orow = out + (size_t)c * HC;
#pragma unroll
    for (int i = 0; i < NEA; i++) {
        float4 v = acc[i];
        v.x = fmaxf(v.x, 0.f); v.y = fmaxf(v.y, 0.f);
        v.z = fmaxf(v.z, 0.f); v.w = fmaxf(v.w, 0.f);
        *(float4*)(orow + i * HDIM + lane * 4) = v;
    }
}

// ---------------- CSR scatter, single channel ----------------
__global__ __launch_bounds__(256) void scatter1_csr_kernel(
    const float* __restrict__ hw, float* __restrict__ out,
    const int* __restrict__ rowptr, const int* __restrict__ csr_r, const int* __restrict__ csr_e,
    const float* __restrict__ ew, const float* __restrict__ dis7,
    const float* __restrict__ bias)
{
    int c = (blockIdx.x * blockDim.x + threadIdx.x) >> 5;
    int lane = threadIdx.x & 31;
    if (c >= N_NODES) return;

    float dc = __ldg(&dis7[c]);
    float4 acc;
    {
        float4 v = *(const float4*)(hw + (size_t)c * HDIM + lane * 4);
        float4 b = *(const float4*)(bias + lane * 4);
        float s = dc * dc;
        acc.x = b.x + s * v.x; acc.y = b.y + s * v.y;
        acc.z = b.z + s * v.z; acc.w = b.w + s * v.w;
    }
    int p0 = __ldg(&rowptr[c]), p1 = __ldg(&rowptr[c + 1]);
    for (int p = p0; p < p1; p++) {
        int r = __ldg(&csr_r[p]);
        int e = __ldg(&csr_e[p]);
        float co = __ldg(&dis7[r]) * dc * __ldg(&ew[e]);
        float4 v = *(const float4*)(hw + (size_t)r * HDIM + lane * 4);
        acc.x += co * v.x; acc.y += co * v.y;
        acc.z += co * v.z; acc.w += co * v.w;
    }
    acc.x = fmaxf(acc.x, 0.f); acc.y = fmaxf(acc.y, 0.f);
    acc.z = fmaxf(acc.z, 0.f); acc.w = fmaxf(acc.w, 0.f);
    *(float4*)(out + (size_t)c * HDIM + lane * 4) = acc;
}

// ---------------- SGEMM with packed fma.rn.f32x2 inner loop ----------------
// BM=BN=128, BK=16, 256 threads, 8x8 per thread (as 8x4 packed pairs), double-buffered.
#define BM 128
#define BN 128
#define BK 16
__global__ __launch_bounds__(256) void sgemm_kernel(
    const float* __restrict__ A, const float* __restrict__ B, float* __restrict__ C,
    int M, int K, int Nc, const float* __restrict__ bias, int flags)
{
    __shared__ float As[2][BK][BM];
    __shared__ float Bs[2][BK][BN];

    const int tid = threadIdx.x;
    const int rowBase = blockIdx.y * BM;
    const int colBase = blockIdx.x * BN;

    const int aRow = tid >> 2;
    const int aCol = (tid & 3) << 2;
    const int bRow = tid >> 5;
    const int bCol = (tid & 31) << 2;

    const int ty = tid >> 4;
    const int tx = tid & 15;

    u64 acc2[8][4];
#pragma unroll
    for (int i = 0; i < 8; i++)
#pragma unroll
        for (int j = 0; j < 4; j++) acc2[i][j] = 0ull;

    const int r0 = rowBase + aRow;
    const int r1 = rowBase + aRow + 64;

    {
        float4 a0 = make_float4(0.f, 0.f, 0.f, 0.f), a1 = a0;
        if (r0 < M) a0 = *(const float4*)(A + (size_t)r0 * K + aCol);
        if (r1 < M) a1 = *(const float4*)(A + (size_t)r1 * K + aCol);
        As[0][aCol + 0][aRow] = a0.x; As[0][aCol + 1][aRow] = a0.y;
        As[0][aCol + 2][aRow] = a0.z; As[0][aCol + 3][aRow] = a0.w;
        As[0][aCol + 0][aRow + 64] = a1.x; As[0][aCol + 1][aRow + 64] = a1.y;
        As[0][aCol + 2][aRow + 64] = a1.z; As[0][aCol + 3][aRow + 64] = a1.w;

        *(float4*)&Bs[0][bRow][bCol]     = *(const float4*)(B + (size_t)bRow * Nc + colBase + bCol);
        *(float4*)&Bs[0][bRow + 8][bCol] = *(const float4*)(B + (size_t)(bRow + 8) * Nc + colBase + bCol);
    }
    __syncthreads();

    int buf = 0;
    for (int k0 = 0; k0 < K; k0 += BK) {
        const int kn = k0 + BK;
        const bool has = kn < K;
        float4 a0, a1, b0, b1;
        if (has) {
            a0 = make_float4(0.f, 0.f, 0.f, 0.f); a1 = a0;
            if (r0 < M) a0 = *(const float4*)(A + (size_t)r0 * K + kn + aCol);
            if (r1 < M) a1 = *(const float4*)(A + (size_t)r1 * K + kn + aCol);
            b0 = *(const float4*)(B + (size_t)(kn + bRow) * Nc + colBase + bCol);
            b1 = *(const float4*)(B + (size_t)(kn + bRow + 8) * Nc + colBase + bCol);
        }

#pragma unroll
        for (int kk = 0; kk < BK; kk++) {
            float a[8];
            *(float4*)&a[0] = *(const float4*)&As[buf][kk][ty * 8];
            *(float4*)&a[4] = *(const float4*)&As[buf][kk][ty * 8 + 4];
            // B pairs read directly as packed 64-bit values (32B-aligned)
            ulonglong2 bq0 = *(const ulonglong2*)&Bs[buf][kk][tx * 8];
            ulonglong2 bq1 = *(const ulonglong2*)&Bs[buf][kk][tx * 8 + 4];
            u64 bp[4] = {bq0.x, bq0.y, bq1.x, bq1.y};
#pragma unroll
            for (int i = 0; i < 8; i++) {
                u64 ad = dup_f32(a[i]);
                ffma2(acc2[i][0], ad, bp[0]);
                ffma2(acc2[i][1], ad, bp[1]);
                ffma2(acc2[i][2], ad, bp[2]);
                ffma2(acc2[i][3], ad, bp[3]);
            }
        }

        if (has) {
            const int nb = buf ^ 1;
            As[nb][aCol + 0][aRow] = a0.x; As[nb][aCol + 1][aRow] = a0.y;
            As[nb][aCol + 2][aRow] = a0.z; As[nb][aCol + 3][aRow] = a0.w;
            As[nb][aCol + 0][aRow + 64] = a1.x; As[nb][aCol + 1][aRow + 64] = a1.y;
            As[nb][aCol + 2][aRow + 64] = a1.z; As[nb][aCol + 3][aRow + 64] = a1.w;
            *(float4*)&Bs[nb][bRow][bCol]     = b0;
            *(float4*)&Bs[nb][bRow + 8][bCol] = b1;
        }
        __syncthreads();
        buf ^= 1;
    }

    float bv[8];
    if (bias) {
#pragma unroll
        for (int j = 0; j < 8; j++) bv[j] = bias[colBase + tx * 8 + j];
    } else {
#pragma unroll
        for (int j = 0; j < 8; j++) bv[j] = 0.f;
    }
    const bool reluO = (flags & 1) != 0;
#pragma unroll
    for (int i = 0; i < 8; i++) {
        int r = rowBase + ty * 8 + i;
        if (r >= M) continue;
        float* crow = C + (size_t)r * Nc + colBase + tx * 8;
        float vr[8];
#pragma unroll
        for (int j = 0; j < 4; j++) {
            float2 p = unpack_f32x2(acc2[i][j]);
            vr[2 * j]     = p.x + bv[2 * j];
            vr[2 * j + 1] = p.y + bv[2 * j + 1];
        }
        if (reluO) {
#pragma unroll
            for (int j = 0; j < 8; j++) vr[j] = fmaxf(vr[j], 0.f);
        }
        *(float4*)crow       = *(float4*)&vr[0];
        *(float4*)(crow + 4) = *(float4*)&vr[4];
    }
}

// ---------------- link head ----------------
__global__ void build_h0_kernel(const float* __restrict__ UV,
                                const float* __restrict__ lb0, const int* __restrict__ eit,
                                float* __restrict__ Hout)
{
    size_t idx = (size_t)blockIdx.x * blockDim.x + threadIdx.x;
    if (idx >= (size_t)2 * ET_EDGES * HLDIM) return;
    int e = (int)(idx >> 7);
    int j = (int)(idx & 127);
    int a, b;
    if (e < ET_EDGES) { a = eit[e]; b = eit[ET_EDGES + e]; }
    else              { int e2 = e - ET_EDGES; a = eit[ET_EDGES + e2]; b = eit[e2]; }
    float v = UV[(size_t)a * 256 + j] + UV[(size_t)b * 256 + 128 + j] + lb0[j];
    Hout[idx] = fmaxf(v, 0.f);
}

__global__ __launch_bounds__(256) void gemm_out_kernel(
    const float* __restrict__ Hm, const float* __restrict__ lw4,
    const float* __restrict__ lb4, float* __restrict__ T, int M)
{
    int w = (blockIdx.x * blockDim.x + threadIdx.x) >> 5;
    int lane = threadIdx.x & 31;
    if (w >= M) return;
    float h0 = Hm[(size_t)w * HLDIM + lane];
    float h1 = Hm[(size_t)w * HLDIM + 32 + lane];
    float h2 = Hm[(size_t)w * HLDIM + 64 + lane];
    float h3 = Hm[(size_t)w * HLDIM + 96 + lane];
    float acc[4];
#pragma unroll
    for (int c = 0; c < 4; c++) {
        acc[c] = h0 * __ldg(&lw4[lane * 4 + c])
               + h1 * __ldg(&lw4[(lane + 32) * 4 + c])
               + h2 * __ldg(&lw4[(lane + 64) * 4 + c])
               + h3 * __ldg(&lw4[(lane + 96) * 4 + c]);
    }
#pragma unroll
    for (int off = 16; off > 0; off >>= 1)
#pragma unroll
        for (int c = 0; c < 4; c++) acc[c] += __shfl_down_sync(0xffffffffu, acc[c], off);
    if (lane == 0) {
#pragma unroll
        for (int c = 0; c < 4; c++) T[(size_t)w * 4 + c] = acc[c] + lb4[c];
    }
}

__global__ void combine_kernel(const float* __restrict__ T, float* __restrict__ out) {
    int idx = blockIdx.x * blockDim.x + threadIdx.x;
    if (idx >= ET_EDGES * 4) return;
    int e = idx >> 2, c = idx & 3;
    int pc = (c == 1) ? 2 : (c == 2) ? 1 : c;
    out[idx] = 0.5f * (T[(size_t)e * 4 + c] + T[(size_t)(ET_EDGES + e) * 4 + pc]);
}

// ---------------- host orchestration ----------------
static inline int cdiv(size_t a, int b) { return (int)((a + b - 1) / b); }

extern "C" void kernel_launch(void* const* d_in, const int* in_sizes, int n_in,
                              void* d_out, int out_size)
{
    const float* x    = (const float*)d_in[0];
    const int*   ei   = (const int*)  d_in[1];
    const float* ea   = (const float*)d_in[2];
    const int*   eit  = (const int*)  d_in[3];
    const float* W0   = (const float*)d_in[4];
    const float* b0   = (const float*)d_in[5];
    const float* W1   = (const float*)d_in[6];
    const float* b1   = (const float*)d_in[7];
    const float* W2   = (const float*)d_in[8];
    const float* b2   = (const float*)d_in[9];
    const float* W3   = (const float*)d_in[10];
    const float* b3   = (const float*)d_in[11];
    const float* ew1  = (const float*)d_in[12];
    const float* eb1  = (const float*)d_in[13];
    const float* ew2  = (const float*)d_in[14];
    const float* eb2  = (const float*)d_in[15];
    const float* ew3  = (const float*)d_in[16];
    const float* eb3  = (const float*)d_in[17];
    const float* lw0  = (const float*)d_in[18];
    const float* lb0  = (const float*)d_in[19];
    const float* lwh  = (const float*)d_in[20];
    const float* lbh  = (const float*)d_in[21];
    const float* lw4  = (const float*)d_in[22];
    const float* lb4  = (const float*)d_in[23];
    float* out = (float*)d_out;

    float *ew, *dis, *W0r, *W2r, *W3r, *Wuv, *hw, *hw128, *x1, *x2b, *x3, *x4, *UV, *Ha, *Hb, *T;
    int *cnt, *cursor, *rowptr, *csr_r, *csr_e;
    cudaGetSymbolAddress((void**)&ew,    g_ew);
    cudaGetSymbolAddress((void**)&dis,   g_dis);
    cudaGetSymbolAddress((void**)&W0r,   g_W0r);
    cudaGetSymbolAddress((void**)&W2r,   g_W2r);
    cudaGetSymbolAddress((void**)&W3r,   g_W3r);
    cudaGetSymbolAddress((void**)&Wuv,   g_Wuv);
    cudaGetSymbolAddress((void**)&hw,    g_hw);
    cudaGetSymbolAddress((void**)&hw128, g_hw128);
    cudaGetSymbolAddress((void**)&x1,    g_x1);
    cudaGetSymbolAddress((void**)&x2b,   g_xb2);
    cudaGetSymbolAddress((void**)&x3,    g_x3);
    cudaGetSymbolAddress((void**)&x4,    g_x4);
    cudaGetSymbolAddress((void**)&UV,    g_UV);
    cudaGetSymbolAddress((void**)&Ha,    g_Ha);
    cudaGetSymbolAddress((void**)&Hb,    g_Hb);
    cudaGetSymbolAddress((void**)&T,     g_T);
    cudaGetSymbolAddress((void**)&cnt,   g_cnt);
    cudaGetSymbolAddress((void**)&cursor,g_cursor);
    cudaGetSymbolAddress((void**)&rowptr,g_rowptr);
    cudaGetSymbolAddress((void**)&csr_r, g_csr_r);
    cudaGetSymbolAddress((void**)&csr_e, g_csr_e);

    const int TB = 256;
    const size_t NW = (size_t)N_NODES * HC;

    // 1) edge-weight MLP
    edge_mlp_kernel<<<cdiv(E_EDGES, TB), TB>>>(ea, ew1, eb1, ew2, eb2, ew3, eb3, ew, E_EDGES);

    // 2) CSR build (by destination)
    zero_int_kernel<<<cdiv(N_NODES, TB), TB>>>(cnt, N_NODES);
    count_kernel<<<cdiv(E_EDGES, TB), TB>>>(ei, cnt, E_EDGES);
    scan_kernel<<<1, 1024>>>(cnt, rowptr, cursor, N_NODES);
    csr_fill_kernel<<<cdiv(E_EDGES, TB), TB>>>(ei, cursor, csr_r, csr_e, E_EDGES);

    // 3) degrees (fused rsqrt)
    deg_csr_kernel<<<cdiv(8 * N_NODES, TB), TB>>>(rowptr, csr_e, ea, ew, dis);

    // 4) pack weights
    pack_w_kernel<<<cdiv(DIN * HC, TB), TB>>>(W0, W0r, DIN);
    pack_w_kernel<<<cdiv(HDIM * HC, TB), TB>>>(W2, W2r, HDIM);
    pack_w_kernel<<<cdiv(HC * HC, TB), TB>>>(W3, W3r, HC);
    pack_uv_kernel<<<cdiv(HC * 256, TB), TB>>>(lw0, Wuv);

    const int SCAT_GRID = cdiv((size_t)N_NODES * 32, TB);

    // ---- layer 1 ----
    gemm_k8_kernel<<<cdiv(NW, TB), TB>>>(x, W0r, hw);
    scatter7_csr_kernel<<<SCAT_GRID, TB>>>(hw, x1, rowptr, csr_r, csr_e, ea, dis, b0);

    // ---- layer 2 (ew norm) ----
    {
        dim3 g(HDIM / BN, cdiv(N_NODES, BM));
        sgemm_kernel<<<g, 256>>>(x1, W1, hw128, N_NODES, HC, HDIM, nullptr, 0);
    }
    scatter1_csr_kernel<<<SCAT_GRID, TB>>>(hw128, x2b, rowptr, csr_r, csr_e, ew,
                                           dis + NEA * N_NODES, b1);

    // ---- layer 3 ----
    {
        dim3 g(HC / BN, cdiv(N_NODES, BM));
        sgemm_kernel<<<g, 256>>>(x2b, W2r, hw, N_NODES, HDIM, HC, nullptr, 0);
    }
    scatter7_csr_kernel<<<SCAT_GRID, TB>>>(hw, x3, rowptr, csr_r, csr_e, ea, dis, b2);

    // ---- layer 4 ----
    {
        dim3 g(HC / BN, cdiv(N_NODES, BM));
        sgemm_kernel<<<g, 256>>>(x3, W3r, hw, N_NODES, HC, HC, nullptr, 0);
    }
    scatter7_csr_kernel<<<SCAT_GRID, TB>>>(hw, x4, rowptr, csr_r, csr_e, ea, dis, b3);

    // ---- link head: UV = x4 @ Wuv ----
    {
        dim3 g(256 / BN, cdiv(N_NODES, BM));
        sgemm_kernel<<<g, 256>>>(x4, Wuv, UV, N_NODES, HC, 256, nullptr, 0);
    }

    const int M2 = 2 * ET_EDGES;
    build_h0_kernel<<<cdiv((size_t)M2 * HLDIM, TB), TB>>>(UV, lb0, eit, Ha);

    {
        dim3 g(HLDIM / BN, cdiv(M2, BM));
        sgemm_kernel<<<g, 256>>>(Ha, lwh,                 Hb, M2, HLDIM, HLDIM, lbh,       1);
        sgemm_kernel<<<g, 256>>>(Hb, lwh + 128 * 128,     Ha, M2, HLDIM, HLDIM, lbh + 128, 1);
        sgemm_kernel<<<g, 256>>>(Ha, lwh + 2 * 128 * 128, Hb, M2, HLDIM, HLDIM, lbh + 256, 1);
    }

    gemm_out_kernel<<<cdiv((size_t)M2 * 32, TB), TB>>>(Hb, lw4, lb4, T, M2);
    combine_kernel<<<cdiv(ET_EDGES * 4, TB), TB>>>(T, out);
}

// round 9
// speedup vs baseline: 1.7734x; 1.4885x over previous
#include <cuda_runtime.h>
#include <cuda_bf16.h>
#include <stdint.h>
#include <math.h>

#define N_NODES 20000
#define E_EDGES 200000
#define ET_EDGES 40000
#define DIN 8
#define HDIM 128
#define NEA 7
#define HC 896
#define HLDIM 128
#define OUTD 4

typedef unsigned long long u64;
typedef unsigned int u32;
typedef __nv_bfloat16 bf16;

// ---------------- scratch ----------------
static __device__ float g_ew[E_EDGES];
static __device__ float g_dis[8 * N_NODES];
static __device__ float g_W0r[DIN * HC];
static __device__ float g_hw[(size_t)N_NODES * HC];
static __device__ float g_hw128[(size_t)N_NODES * HDIM];
static __device__ float g_UV[(size_t)N_NODES * 256];
static __device__ float g_Hb_f32[(size_t)2 * ET_EDGES * HLDIM];
static __device__ float g_T[(size_t)2 * ET_EDGES * OUTD];
static __device__ bf16 g_x1h[(size_t)N_NODES * HC];
static __device__ bf16 g_x1l[(size_t)N_NODES * HC];
static __device__ bf16 g_x2h[(size_t)N_NODES * HDIM];
static __device__ bf16 g_x2l[(size_t)N_NODES * HDIM];
static __device__ bf16 g_x3h[(size_t)N_NODES * HC];
static __device__ bf16 g_x3l[(size_t)N_NODES * HC];
static __device__ bf16 g_x4h[(size_t)N_NODES * HC];
static __device__ bf16 g_x4l[(size_t)N_NODES * HC];
static __device__ bf16 g_Hah[(size_t)2 * ET_EDGES * HLDIM];
static __device__ bf16 g_Hal[(size_t)2 * ET_EDGES * HLDIM];
static __device__ bf16 g_Hbh[(size_t)2 * ET_EDGES * HLDIM];
static __device__ bf16 g_Hbl[(size_t)2 * ET_EDGES * HLDIM];
static __device__ bf16 g_B1h[HDIM * HC];
static __device__ bf16 g_B1l[HDIM * HC];
static __device__ bf16 g_B2h[HC * HDIM];
static __device__ bf16 g_B2l[HC * HDIM];
static __device__ bf16 g_B3h[(size_t)HC * HC];
static __device__ bf16 g_B3l[(size_t)HC * HC];
static __device__ bf16 g_Buvh[256 * HC];
static __device__ bf16 g_Buvl[256 * HC];
static __device__ bf16 g_Blhh[3 * HLDIM * HLDIM];
static __device__ bf16 g_Blhl[3 * HLDIM * HLDIM];
static __device__ int g_cnt[N_NODES];
static __device__ int g_cursor[N_NODES];
static __device__ int g_rowptr[N_NODES + 1];
static __device__ int g_csr_r[E_EDGES];
static __device__ int g_csr_e[E_EDGES];

// ---------------- bf16 split helpers ----------------
__device__ __forceinline__ void split1(float v, bf16* ph, bf16* pl) {
    bf16 h = __float2bfloat16(v);
    *ph = h;
    *pl = __float2bfloat16(v - __bfloat162float(h));
}
__device__ __forceinline__ void split_store4(bf16* ph, bf16* pl, float4 v) {
    bf16 h0 = __float2bfloat16(v.x);
    bf16 h1 = __float2bfloat16(v.y);
    bf16 h2 = __float2bfloat16(v.z);
    bf16 h3 = __float2bfloat16(v.w);
    bf16 l0 = __float2bfloat16(v.x - __bfloat162float(h0));
    bf16 l1 = __float2bfloat16(v.y - __bfloat162float(h1));
    bf16 l2 = __float2bfloat16(v.z - __bfloat162float(h2));
    bf16 l3 = __float2bfloat16(v.w - __bfloat162float(h3));
    __nv_bfloat162* H = reinterpret_cast<__nv_bfloat162*>(ph);
    __nv_bfloat162* L = reinterpret_cast<__nv_bfloat162*>(pl);
    H[0] = __halves2bfloat162(h0, h1);
    H[1] = __halves2bfloat162(h2, h3);
    L[0] = __halves2bfloat162(l0, l1);
    L[1] = __halves2bfloat162(l2, l3);
}
__device__ __forceinline__ void split_store2(bf16* ph, bf16* pl, float x, float y) {
    bf16 hx = __float2bfloat16(x);
    bf16 hy = __float2bfloat16(y);
    bf16 lx = __float2bfloat16(x - __bfloat162float(hx));
    bf16 ly = __float2bfloat16(y - __bfloat162float(hy));
    *reinterpret_cast<__nv_bfloat162*>(ph) = __halves2bfloat162(hx, hy);
    *reinterpret_cast<__nv_bfloat162*>(pl) = __halves2bfloat162(lx, ly);
}

// ---------------- bf16 mma.sync GEMM ----------------
// C[M,Nc] = A[M,K] @ B[Nc,K]^T with A,B as bf16 (hi,lo) pairs.
// Computes AhBh + AhBl + AlBh with fp32 accumulators (AlBl term ~2^-18, dropped).
// flags: bit0 relu, bit1 write fp32 C, bit2 write bf16 pair CH/CL.
#define GBK 32
#define ASTR 40                 // padded smem row stride (80B = 20 banks, conflict-free)
#define TSZ (128 * ASTR)        // one tile: 128 rows x ASTR bf16
#define MMA_SMEM (2 * 4 * TSZ * 2)   // 2 buffers x 4 tiles x TSZ bf16 x 2B = 81920

#define MMA_BF16(d, a, b0v, b1v) \
    asm volatile("mma.sync.aligned.m16n8k16.row.col.f32.bf16.bf16.f32 " \
        "{%0,%1,%2,%3}, {%4,%5,%6,%7}, {%8,%9}, {%0,%1,%2,%3};" \
        : "+f"((d)[0]), "+f"((d)[1]), "+f"((d)[2]), "+f"((d)[3]) \
        : "r"((a)[0]), "r"((a)[1]), "r"((a)[2]), "r"((a)[3]), "r"(b0v), "r"(b1v))

__device__ __forceinline__ void gm_load(
    uint4* rg, const bf16* Ah, const bf16* Al, const bf16* Bh, const bf16* Bl,
    int rowBase, int colBase, int M, int K, int kb, int r0, int r1, int kv)
{
    uint4 z = make_uint4(0u, 0u, 0u, 0u);
    size_t a0 = (size_t)(rowBase + r0) * K + kb + kv;
    size_t a1 = (size_t)(rowBase + r1) * K + kb + kv;
    bool g0 = (rowBase + r0) < M;
    bool g1 = (rowBase + r1) < M;
    rg[0] = g0 ? *(const uint4*)(Ah + a0) : z;
    rg[1] = g1 ? *(const uint4*)(Ah + a1) : z;
    rg[2] = g0 ? *(const uint4*)(Al + a0) : z;
    rg[3] = g1 ? *(const uint4*)(Al + a1) : z;
    size_t b0 = (size_t)(colBase + r0) * K + kb + kv;
    size_t b1 = (size_t)(colBase + r1) * K + kb + kv;
    rg[4] = *(const uint4*)(Bh + b0);
    rg[5] = *(const uint4*)(Bh + b1);
    rg[6] = *(const uint4*)(Bl + b0);
    rg[7] = *(const uint4*)(Bl + b1);
}
__device__ __forceinline__ void sm_store(bf16* sm, const uint4* rg, int buf, int r0, int r1, int kv)
{
    bf16* base = sm + buf * 4 * TSZ;
    *(uint4*)(base + 0 * TSZ + r0 * ASTR + kv) = rg[0];
    *(uint4*)(base + 0 * TSZ + r1 * ASTR + kv) = rg[1];
    *(uint4*)(base + 1 * TSZ + r0 * ASTR + kv) = rg[2];
    *(uint4*)(base + 1 * TSZ + r1 * ASTR + kv) = rg[3];
    *(uint4*)(base + 2 * TSZ + r0 * ASTR + kv) = rg[4];
    *(uint4*)(base + 2 * TSZ + r1 * ASTR + kv) = rg[5];
    *(uint4*)(base + 3 * TSZ + r0 * ASTR + kv) = rg[6];
    *(uint4*)(base + 3 * TSZ + r1 * ASTR + kv) = rg[7];
}

__global__ __launch_bounds__(256)
void gemm_mma_kernel(
    const bf16* __restrict__ Ah, const bf16* __restrict__ Al,
    const bf16* __restrict__ Bh, const bf16* __restrict__ Bl,
    float* __restrict__ C, bf16* __restrict__ CH, bf16* __restrict__ CL,
    int M, int K, int Nc, const float* __restrict__ bias, int flags)
{
    extern __shared__ bf16 sm[];
    const int tid = threadIdx.x;
    const int wid = tid >> 5;
    const int lane = tid & 31;
    const int rowBase = blockIdx.y * 128;
    const int colBase = blockIdx.x * 128;
    const int wRow = (wid & 3) * 32;
    const int wCol = (wid >> 2) * 64;
    const int ar = lane >> 2;        // fragment row/col group
    const int ac = (lane & 3) << 1;  // fragment k-pair index

    const int lr0 = tid >> 2;        // loader rows 0..63
    const int lr1 = lr0 + 64;
    const int lkv = (tid & 3) << 3;  // loader k offset 0,8,16,24

    float acc[2][8][4];
#pragma unroll
    for (int i = 0; i < 2; i++)
#pragma unroll
        for (int j = 0; j < 8; j++)
#pragma unroll
            for (int q = 0; q < 4; q++) acc[i][j][q] = 0.f;

    // prologue
    {
        uint4 rg[8];
        gm_load(rg, Ah, Al, Bh, Bl, rowBase, colBase, M, K, 0, lr0, lr1, lkv);
        sm_store(sm, rg, 0, lr0, lr1, lkv);
    }
    __syncthreads();

    const int NKB = K / GBK;
    int buf = 0;
    for (int kb = 0; kb < NKB; kb++) {
        uint4 rg[8];
        const bool has = (kb + 1) < NKB;
        if (has) {
            gm_load(rg, Ah, Al, Bh, Bl, rowBase, colBase, M, K, (kb + 1) * GBK, lr0, lr1, lkv);
        }

        const bf16* base = sm + buf * 4 * TSZ;
#pragma unroll
        for (int ks = 0; ks < 2; ks++) {
            const int k0 = ks * 16;
            // A fragments: [rt][h][4]
            u32 afr[2][2][4];
#pragma unroll
            for (int rt = 0; rt < 2; rt++) {
#pragma unroll
                for (int h = 0; h < 2; h++) {
                    const bf16* p = base + h * TSZ + (wRow + rt * 16 + ar) * ASTR + k0 + ac;
                    afr[rt][h][0] = *(const u32*)p;
                    afr[rt][h][1] = *(const u32*)(p + 8 * ASTR);
                    afr[rt][h][2] = *(const u32*)(p + 8);
                    afr[rt][h][3] = *(const u32*)(p + 8 * ASTR + 8);
                }
            }
#pragma unroll
            for (int ct = 0; ct < 8; ct++) {
                const bf16* q = base + 2 * TSZ + (wCol + ct * 8 + ar) * ASTR + k0 + ac;
                u32 bh0 = *(const u32*)q;
                u32 bh1 = *(const u32*)(q + 8);
                u32 bl0 = *(const u32*)(q + TSZ);
                u32 bl1 = *(const u32*)(q + TSZ + 8);
#pragma unroll
                for (int rt = 0; rt < 2; rt++) {
                    MMA_BF16(acc[rt][ct], afr[rt][0], bh0, bh1);  // hi*hi
                    MMA_BF16(acc[rt][ct], afr[rt][0], bl0, bl1);  // hi*lo
                    MMA_BF16(acc[rt][ct], afr[rt][1], bh0, bh1);  // lo*hi
                }
            }
        }

        if (has) {
            __syncthreads();
            sm_store(sm, rg, buf ^ 1, lr0, lr1, lkv);
            __syncthreads();
        }
        buf ^= 1;
    }

    // epilogue
    const int doRelu = flags & 1;
    const int wF = flags & 2;
    const int wP = flags & 4;
#pragma unroll
    for (int rt = 0; rt < 2; rt++) {
#pragma unroll
        for (int ct = 0; ct < 8; ct++) {
            int r = rowBase + wRow + rt * 16 + ar;
            int c = colBase + wCol + ct * 8 + ac;
            float b0v = bias ? __ldg(&bias[c]) : 0.f;
            float b1v = bias ? __ldg(&bias[c + 1]) : 0.f;
            float v0 = acc[rt][ct][0] + b0v;
            float v1 = acc[rt][ct][1] + b1v;
            float v2 = acc[rt][ct][2] + b0v;
            float v3 = acc[rt][ct][3] + b1v;
            if (doRelu) {
                v0 = fmaxf(v0, 0.f); v1 = fmaxf(v1, 0.f);
                v2 = fmaxf(v2, 0.f); v3 = fmaxf(v3, 0.f);
            }
            if (r < M) {
                size_t o = (size_t)r * Nc + c;
                if (wF) *(float2*)(C + o) = make_float2(v0, v1);
                if (wP) split_store2(CH + o, CL + o, v0, v1);
            }
            if (r + 8 < M) {
                size_t o = (size_t)(r + 8) * Nc + c;
                if (wF) *(float2*)(C + o) = make_float2(v2, v3);
                if (wP) split_store2(CH + o, CL + o, v2, v3);
            }
        }
    }
}

// ---------------- edge-weight MLP ----------------
__global__ __launch_bounds__(256) void edge_mlp_kernel(
    const float* __restrict__ ea,
    const float* __restrict__ w1, const float* __restrict__ bb1,
    const float* __restrict__ w2, const float* __restrict__ bb2,
    const float* __restrict__ w3, const float* __restrict__ bb3,
    float* __restrict__ out, int E)
{
    __shared__ float s1[NEA * 28];
    __shared__ float sb1[28];
    __shared__ float s2[28 * 28];
    __shared__ float sb2[28];
    __shared__ float s3[28];
    __shared__ float sb3v[1];
    for (int i = threadIdx.x; i < NEA * 28; i += blockDim.x) s1[i] = w1[i];
    for (int i = threadIdx.x; i < 28; i += blockDim.x) {
        sb1[i] = bb1[i];
        sb2[i] = bb2[i];
        s3[i] = w3[i];
    }
    for (int i = threadIdx.x; i < 28 * 28; i += blockDim.x) s2[i] = w2[i];
    if (threadIdx.x == 0) sb3v[0] = bb3[0];
    __syncthreads();

    int e = blockIdx.x * blockDim.x + threadIdx.x;
    if (e >= E) return;
    float a[NEA];
#pragma unroll
    for (int k = 0; k < NEA; k++) a[k] = ea[(size_t)e * NEA + k];
    float t[28];
#pragma unroll
    for (int j = 0; j < 28; j++) {
        float v = sb1[j];
#pragma unroll
        for (int k = 0; k < NEA; k++) v += a[k] * s1[k * 28 + j];
        t[j] = fmaxf(v, 0.f);
    }
    float u[28];
#pragma unroll
    for (int j = 0; j < 28; j++) {
        float v = sb2[j];
#pragma unroll
        for (int k = 0; k < 28; k++) v += t[k] * s2[k * 28 + j];
        u[j] = fmaxf(v, 0.f);
    }
    float z = sb3v[0];
#pragma unroll
    for (int k = 0; k < 28; k++) z += u[k] * s3[k];
    out[e] = 1.f / (1.f + expf(-z));
}

// ---------------- CSR build ----------------
__global__ void zero_int_kernel(int* __restrict__ p, int n) {
    int i = blockIdx.x * blockDim.x + threadIdx.x;
    if (i < n) p[i] = 0;
}
__global__ void count_kernel(const int* __restrict__ ei, int* __restrict__ cnt, int E) {
    int e = blockIdx.x * blockDim.x + threadIdx.x;
    if (e < E) atomicAdd(&cnt[ei[E + e]], 1);
}
__global__ __launch_bounds__(1024) void scan_kernel(
    const int* __restrict__ cnt, int* __restrict__ rowptr, int* __restrict__ cursor, int n)
{
    __shared__ int warpsum[32];
    const int t = threadIdx.x;
    const int lane = t & 31;
    const int wrp = t >> 5;
    const int C = (n + 1023) / 1024;
    const int base = t * C;
    int local = 0;
    for (int i = 0; i < C; i++) {
        int idx = base + i;
        if (idx < n) local += cnt[idx];
    }
    int sc = local;
#pragma unroll
    for (int off = 1; off < 32; off <<= 1) {
        int v = __shfl_up_sync(0xffffffffu, sc, off);
        if (lane >= off) sc += v;
    }
    if (lane == 31) warpsum[wrp] = sc;
    __syncthreads();
    if (wrp == 0) {
        int ws = warpsum[lane];
#pragma unroll
        for (int off = 1; off < 32; off <<= 1) {
            int v = __shfl_up_sync(0xffffffffu, ws, off);
            if (lane >= off) ws += v;
        }
        warpsum[lane] = ws;
    }
    __syncthreads();
    int run = (wrp > 0 ? warpsum[wrp - 1] : 0) + (sc - local);
    if (t == 0) rowptr[0] = 0;
    for (int i = 0; i < C; i++) {
        int idx = base + i;
        if (idx < n) {
            cursor[idx] = run;
            run += cnt[idx];
            rowptr[idx + 1] = run;
        }
    }
}
__global__ void csr_fill_kernel(const int* __restrict__ ei, int* __restrict__ cursor,
                                int* __restrict__ csr_r, int* __restrict__ csr_e, int E)
{
    int e = blockIdx.x * blockDim.x + threadIdx.x;
    if (e >= E) return;
    int r = ei[e];
    int c = ei[E + e];
    int pos = atomicAdd(&cursor[c], 1);
    csr_r[pos] = r;
    csr_e[pos] = e;
}

// ---------------- degrees via CSR ----------------
__global__ void deg_csr_kernel(const int* __restrict__ rowptr, const int* __restrict__ csr_e,
                               const float* __restrict__ ea, const float* __restrict__ ew,
                               float* __restrict__ dis)
{
    int idx = blockIdx.x * blockDim.x + threadIdx.x;
    if (idx >= 8 * N_NODES) return;
    int i = idx / N_NODES;
    int v = idx % N_NODES;
    int p0 = rowptr[v];
    int p1 = rowptr[v + 1];
    float s = 1.0f;
    if (i < NEA) {
        for (int p = p0; p < p1; p++) s += __ldg(&ea[(size_t)csr_e[p] * NEA + i]);
    } else {
        for (int p = p0; p < p1; p++) s += __ldg(&ew[csr_e[p]]);
    }
    dis[idx] = rsqrtf(s);
}

// ---------------- weight packs ----------------
__global__ void pack_w_kernel(const float* __restrict__ in, float* __restrict__ out, int K) {
    int idx = blockIdx.x * blockDim.x + threadIdx.x;
    if (idx >= K * HC) return;
    int k = idx / HC;
    int c = idx % HC;
    int i = c >> 7;
    int j = c & 127;
    out[idx] = in[((size_t)i * K + k) * HDIM + j];
}
__global__ void pack_b1_kernel(const float* __restrict__ W1, bf16* __restrict__ Bh, bf16* __restrict__ Bl) {
    int idx = blockIdx.x * blockDim.x + threadIdx.x;
    if (idx >= HDIM * HC) return;
    int n = idx / HC;
    int k = idx % HC;
    split1(W1[(size_t)k * HDIM + n], &Bh[idx], &Bl[idx]);
}
__global__ void pack_b2_kernel(const float* __restrict__ W2, bf16* __restrict__ Bh, bf16* __restrict__ Bl) {
    int idx = blockIdx.x * blockDim.x + threadIdx.x;
    if (idx >= HC * HDIM) return;
    int c = idx / HDIM;
    int k = idx % HDIM;
    int i = c >> 7;
    int j = c & 127;
    split1(W2[((size_t)i * HDIM + k) * HDIM + j], &Bh[idx], &Bl[idx]);
}
__global__ void pack_b3_kernel(const float* __restrict__ W3, bf16* __restrict__ Bh, bf16* __restrict__ Bl) {
    int idx = blockIdx.x * blockDim.x + threadIdx.x;
    if (idx >= HC * HC) return;
    int c = idx / HC;
    int k = idx % HC;
    int i = c >> 7;
    int j = c & 127;
    split1(W3[((size_t)i * HC + k) * HDIM + j], &Bh[idx], &Bl[idx]);
}
__global__ void pack_buv_kernel(const float* __restrict__ lw0, bf16* __restrict__ Bh, bf16* __restrict__ Bl) {
    int idx = blockIdx.x * blockDim.x + threadIdx.x;
    if (idx >= 256 * HC) return;
    int c = idx / HC;
    int k = idx % HC;
    float v = (c < 128) ? lw0[(size_t)k * 128 + c] : lw0[(size_t)(HC + k) * 128 + (c - 128)];
    split1(v, &Bh[idx], &Bl[idx]);
}
__global__ void pack_blh_kernel(const float* __restrict__ lwh, bf16* __restrict__ Bh, bf16* __restrict__ Bl) {
    int idx = blockIdx.x * blockDim.x + threadIdx.x;
    if (idx >= 3 * HLDIM * HLDIM) return;
    int i = idx / (HLDIM * HLDIM);
    int n = (idx / HLDIM) % HLDIM;
    int k = idx % HLDIM;
    split1(lwh[((size_t)i * HLDIM + k) * HLDIM + n], &Bh[idx], &Bl[idx]);
}

// ---------------- G0: x[N,8] @ W0r[8,896] (fp32) ----------------
__global__ void gemm_k8_kernel(const float* __restrict__ x, const float* __restrict__ W,
                               float* __restrict__ out)
{
    int idx = blockIdx.x * blockDim.x + threadIdx.x;
    if (idx >= N_NODES * HC) return;
    int m = idx / HC;
    int c = idx % HC;
    float v = 0.f;
#pragma unroll
    for (int k = 0; k < DIN; k++) v += __ldg(&x[m * DIN + k]) * W[k * HC + c];
    out[idx] = v;
}

// ---------------- CSR scatter, 7-channel -> bf16 pair ----------------
__global__ __launch_bounds__(256) void scatter7_csr_kernel(
    const float* __restrict__ hw, bf16* __restrict__ outH, bf16* __restrict__ outL,
    const int* __restrict__ rowptr, const int* __restrict__ csr_r, const int* __restrict__ csr_e,
    const float* __restrict__ ea, const float* __restrict__ dis,
    const float* __restrict__ bias)
{
    int c = (blockIdx.x * blockDim.x + threadIdx.x) >> 5;
    int lane = threadIdx.x & 31;
    if (c >= N_NODES) return;

    float dci = (lane < NEA) ? __ldg(&dis[lane * N_NODES + c]) : 0.f;
    float dc[NEA];
#pragma unroll
    for (int i = 0; i < NEA; i++) dc[i] = __shfl_sync(0xffffffffu, dci, i);

    float4 acc[NEA];
    const float* srow = hw + (size_t)c * HC;
#pragma unroll
    for (int i = 0; i < NEA; i++) {
        float4 v = *(const float4*)(srow + i * HDIM + lane * 4);
        float4 b = *(const float4*)(bias + i * HDIM + lane * 4);
        float s = dc[i] * dc[i];
        acc[i].x = b.x + s * v.x;
        acc[i].y = b.y + s * v.y;
        acc[i].z = b.z + s * v.z;
        acc[i].w = b.w + s * v.w;
    }

    int p0 = __ldg(&rowptr[c]);
    int p1 = __ldg(&rowptr[c + 1]);
    for (int p = p0; p < p1; p++) {
        int r = __ldg(&csr_r[p]);
        int e = __ldg(&csr_e[p]);
        float cof = (lane < NEA)
            ? __ldg(&dis[lane * N_NODES + r]) * __ldg(&ea[(size_t)e * NEA + lane])
            : 0.f;
        float co[NEA];
#pragma unroll
        for (int i = 0; i < NEA; i++) co[i] = __shfl_sync(0xffffffffu, cof, i) * dc[i];
        const float* rr = hw + (size_t)r * HC;
#pragma unroll
        for (int i = 0; i < NEA; i++) {
            float4 v = *(const float4*)(rr + i * HDIM + lane * 4);
            acc[i].x += co[i] * v.x;
            acc[i].y += co[i] * v.y;
            acc[i].z += co[i] * v.z;
            acc[i].w += co[i] * v.w;
        }
    }

#pragma unroll
    for (int i = 0; i < NEA; i++) {
        float4 v = acc[i];
        v.x = fmaxf(v.x, 0.f);
        v.y = fmaxf(v.y, 0.f);
        v.z = fmaxf(v.z, 0.f);
        v.w = fmaxf(v.w, 0.f);
        size_t o = (size_t)c * HC + i * HDIM + lane * 4;
        split_store4(outH + o, outL + o, v);
    }
}

// ---------------- CSR scatter, single channel -> bf16 pair ----------------
__global__ __launch_bounds__(256) void scatter1_csr_kernel(
    const float* __restrict__ hw, bf16* __restrict__ outH, bf16* __restrict__ outL,
    const int* __restrict__ rowptr, const int* __restrict__ csr_r, const int* __restrict__ csr_e,
    const float* __restrict__ ewv, const float* __restrict__ dis7,
    const float* __restrict__ bias)
{
    int c = (blockIdx.x * blockDim.x + threadIdx.x) >> 5;
    int lane = threadIdx.x & 31;
    if (c >= N_NODES) return;

    float dc = __ldg(&dis7[c]);
    float4 acc;
    {
        float4 v = *(const float4*)(hw + (size_t)c * HDIM + lane * 4);
        float4 b = *(const float4*)(bias + lane * 4);
        float s = dc * dc;
        acc.x = b.x + s * v.x;
        acc.y = b.y + s * v.y;
        acc.z = b.z + s * v.z;
        acc.w = b.w + s * v.w;
    }
    int p0 = __ldg(&rowptr[c]);
    int p1 = __ldg(&rowptr[c + 1]);
    for (int p = p0; p < p1; p++) {
        int r = __ldg(&csr_r[p]);
        int e = __ldg(&csr_e[p]);
        float co = __ldg(&dis7[r]) * dc * __ldg(&ewv[e]);
        float4 v = *(const float4*)(hw + (size_t)r * HDIM + lane * 4);
        acc.x += co * v.x;
        acc.y += co * v.y;
        acc.z += co * v.z;
        acc.w += co * v.w;
    }
    acc.x = fmaxf(acc.x, 0.f);
    acc.y = fmaxf(acc.y, 0.f);
    acc.z = fmaxf(acc.z, 0.f);
    acc.w = fmaxf(acc.w, 0.f);
    size_t o = (size_t)c * HDIM + lane * 4;
    split_store4(outH + o, outL + o, acc);
}

// ---------------- link head ----------------
__global__ void build_h0_kernel(const float* __restrict__ UV,
                                const float* __restrict__ lb0, const int* __restrict__ eit,
                                bf16* __restrict__ Hh, bf16* __restrict__ Hl)
{
    size_t idx = (size_t)blockIdx.x * blockDim.x + threadIdx.x;
    if (idx >= (size_t)2 * ET_EDGES * HLDIM) return;
    int e = (int)(idx >> 7);
    int j = (int)(idx & 127);
    int a;
    int b;
    if (e < ET_EDGES) {
        a = eit[e];
        b = eit[ET_EDGES + e];
    } else {
        int e2 = e - ET_EDGES;
        a = eit[ET_EDGES + e2];
        b = eit[e2];
    }
    float v = UV[(size_t)a * 256 + j] + UV[(size_t)b * 256 + 128 + j] + lb0[j];
    v = fmaxf(v, 0.f);
    split1(v, &Hh[idx], &Hl[idx]);
}

__global__ __launch_bounds__(256) void gemm_out_kernel(
    const float* __restrict__ Hm, const float* __restrict__ lw4,
    const float* __restrict__ lb4, float* __restrict__ T, int M)
{
    int w = (blockIdx.x * blockDim.x + threadIdx.x) >> 5;
    int lane = threadIdx.x & 31;
    if (w >= M) return;
    float h0 = Hm[(size_t)w * HLDIM + lane];
    float h1 = Hm[(size_t)w * HLDIM + 32 + lane];
    float h2 = Hm[(size_t)w * HLDIM + 64 + lane];
    float h3 = Hm[(size_t)w * HLDIM + 96 + lane];
    float acc[4];
#pragma unroll
    for (int c = 0; c < 4; c++) {
        acc[c] = h0 * __ldg(&lw4[lane * 4 + c])
               + h1 * __ldg(&lw4[(lane + 32) * 4 + c])
               + h2 * __ldg(&lw4[(lane + 64) * 4 + c])
               + h3 * __ldg(&lw4[(lane + 96) * 4 + c]);
    }
#pragma unroll
    for (int off = 16; off > 0; off >>= 1) {
#pragma unroll
        for (int c = 0; c < 4; c++) acc[c] += __shfl_down_sync(0xffffffffu, acc[c], off);
    }
    if (lane == 0) {
#pragma unroll
        for (int c = 0; c < 4; c++) T[(size_t)w * 4 + c] = acc[c] + lb4[c];
    }
}

__global__ void combine_kernel(const float* __restrict__ T, float* __restrict__ out) {
    int idx = blockIdx.x * blockDim.x + threadIdx.x;
    if (idx >= ET_EDGES * 4) return;
    int e = idx >> 2;
    int c = idx & 3;
    int pc = (c == 1) ? 2 : ((c == 2) ? 1 : c);
    out[idx] = 0.5f * (T[(size_t)e * 4 + c] + T[(size_t)(ET_EDGES + e) * 4 + pc]);
}

// ---------------- host orchestration ----------------
static inline int cdiv(size_t a, int b) { return (int)((a + b - 1) / b); }

extern "C" void kernel_launch(void* const* d_in, const int* in_sizes, int n_in,
                              void* d_out, int out_size)
{
    const float* x    = (const float*)d_in[0];
    const int*   ei   = (const int*)  d_in[1];
    const float* ea   = (const float*)d_in[2];
    const int*   eit  = (const int*)  d_in[3];
    const float* W0   = (const float*)d_in[4];
    const float* b0   = (const float*)d_in[5];
    const float* W1   = (const float*)d_in[6];
    const float* b1   = (const float*)d_in[7];
    const float* W2   = (const float*)d_in[8];
    const float* b2   = (const float*)d_in[9];
    const float* W3   = (const float*)d_in[10];
    const float* b3   = (const float*)d_in[11];
    const float* ew1  = (const float*)d_in[12];
    const float* eb1  = (const float*)d_in[13];
    const float* ew2  = (const float*)d_in[14];
    const float* eb2  = (const float*)d_in[15];
    const float* ew3  = (const float*)d_in[16];
    const float* eb3  = (const float*)d_in[17];
    const float* lw0  = (const float*)d_in[18];
    const float* lb0  = (const float*)d_in[19];
    const float* lwh  = (const float*)d_in[20];
    const float* lbh  = (const float*)d_in[21];
    const float* lw4  = (const float*)d_in[22];
    const float* lb4  = (const float*)d_in[23];
    float* out = (float*)d_out;

    float *ew, *dis, *W0r, *hw, *hw128, *UV, *Hbf, *T;
    bf16 *x1h, *x1l, *x2h, *x2l, *x3h, *x3l, *x4h, *x4l;
    bf16 *Hah, *Hal, *Hbh, *Hbl;
    bf16 *B1h, *B1l, *B2h, *B2l, *B3h, *B3l, *Buvh, *Buvl, *Blhh, *Blhl;
    int *cnt, *cursor, *rowptr, *csr_r, *csr_e;
    cudaGetSymbolAddress((void**)&ew,    g_ew);
    cudaGetSymbolAddress((void**)&dis,   g_dis);
    cudaGetSymbolAddress((void**)&W0r,   g_W0r);
    cudaGetSymbolAddress((void**)&hw,    g_hw);
    cudaGetSymbolAddress((void**)&hw128, g_hw128);
    cudaGetSymbolAddress((void**)&UV,    g_UV);
    cudaGetSymbolAddress((void**)&Hbf,   g_Hb_f32);
    cudaGetSymbolAddress((void**)&T,     g_T);
    cudaGetSymbolAddress((void**)&x1h,   g_x1h);
    cudaGetSymbolAddress((void**)&x1l,   g_x1l);
    cudaGetSymbolAddress((void**)&x2h,   g_x2h);
    cudaGetSymbolAddress((void**)&x2l,   g_x2l);
    cudaGetSymbolAddress((void**)&x3h,   g_x3h);
    cudaGetSymbolAddress((void**)&x3l,   g_x3l);
    cudaGetSymbolAddress((void**)&x4h,   g_x4h);
    cudaGetSymbolAddress((void**)&x4l,   g_x4l);
    cudaGetSymbolAddress((void**)&Hah,   g_Hah);
    cudaGetSymbolAddress((void**)&Hal,   g_Hal);
    cudaGetSymbolAddress((void**)&Hbh,   g_Hbh);
    cudaGetSymbolAddress((void**)&Hbl,   g_Hbl);
    cudaGetSymbolAddress((void**)&B1h,   g_B1h);
    cudaGetSymbolAddress((void**)&B1l,   g_B1l);
    cudaGetSymbolAddress((void**)&B2h,   g_B2h);
    cudaGetSymbolAddress((void**)&B2l,   g_B2l);
    cudaGetSymbolAddress((void**)&B3h,   g_B3h);
    cudaGetSymbolAddress((void**)&B3l,   g_B3l);
    cudaGetSymbolAddress((void**)&Buvh,  g_Buvh);
    cudaGetSymbolAddress((void**)&Buvl,  g_Buvl);
    cudaGetSymbolAddress((void**)&Blhh,  g_Blhh);
    cudaGetSymbolAddress((void**)&Blhl,  g_Blhl);
    cudaGetSymbolAddress((void**)&cnt,   g_cnt);
    cudaGetSymbolAddress((void**)&cursor,g_cursor);
    cudaGetSymbolAddress((void**)&rowptr,g_rowptr);
    cudaGetSymbolAddress((void**)&csr_r, g_csr_r);
    cudaGetSymbolAddress((void**)&csr_e, g_csr_e);

    cudaFuncSetAttribute(gemm_mma_kernel, cudaFuncAttributeMaxDynamicSharedMemorySize, MMA_SMEM);

    const int TB = 256;
    const size_t NW = (size_t)N_NODES * HC;
    const int M2 = 2 * ET_EDGES;

    edge_mlp_kernel<<<cdiv(E_EDGES, TB), TB>>>(ea, ew1, eb1, ew2, eb2, ew3, eb3, ew, E_EDGES);

    zero_int_kernel<<<cdiv(N_NODES, TB), TB>>>(cnt, N_NODES);
    count_kernel<<<cdiv(E_EDGES, TB), TB>>>(ei, cnt, E_EDGES);
    scan_kernel<<<1, 1024>>>(cnt, rowptr, cursor, N_NODES);
    csr_fill_kernel<<<cdiv(E_EDGES, TB), TB>>>(ei, cursor, csr_r, csr_e, E_EDGES);

    deg_csr_kernel<<<cdiv(8 * N_NODES, TB), TB>>>(rowptr, csr_e, ea, ew, dis);

    pack_w_kernel<<<cdiv(DIN * HC, TB), TB>>>(W0, W0r, DIN);
    pack_b1_kernel<<<cdiv(HDIM * HC, TB), TB>>>(W1, B1h, B1l);
    pack_b2_kernel<<<cdiv(HC * HDIM, TB), TB>>>(W2, B2h, B2l);
    pack_b3_kernel<<<cdiv((size_t)HC * HC, TB), TB>>>(W3, B3h, B3l);
    pack_buv_kernel<<<cdiv(256 * HC, TB), TB>>>(lw0, Buvh, Buvl);
    pack_blh_kernel<<<cdiv(3 * HLDIM * HLDIM, TB), TB>>>(lwh, Blhh, Blhl);

    const int SCAT_GRID = cdiv((size_t)N_NODES * 32, TB);
    const int GRY = cdiv(N_NODES, 128);

    // layer 1
    gemm_k8_kernel<<<cdiv(NW, TB), TB>>>(x, W0r, hw);
    scatter7_csr_kernel<<<SCAT_GRID, TB>>>(hw, x1h, x1l, rowptr, csr_r, csr_e, ea, dis, b0);

    // layer 2
    gemm_mma_kernel<<<dim3(1, GRY), 256, MMA_SMEM>>>(
        x1h, x1l, B1h, B1l, hw128, (bf16*)0, (bf16*)0, N_NODES, HC, HDIM, (const float*)0, 2);
    scatter1_csr_kernel<<<SCAT_GRID, TB>>>(hw128, x2h, x2l, rowptr, csr_r, csr_e, ew,
                                           dis + NEA * N_NODES, b1);

    // layer 3
    gemm_mma_kernel<<<dim3(7, GRY), 256, MMA_SMEM>>>(
        x2h, x2l, B2h, B2l, hw, (bf16*)0, (bf16*)0, N_NODES, HDIM, HC, (const float*)0, 2);
    scatter7_csr_kernel<<<SCAT_GRID, TB>>>(hw, x3h, x3l, rowptr, csr_r, csr_e, ea, dis, b2);

    // layer 4
    gemm_mma_kernel<<<dim3(7, GRY), 256, MMA_SMEM>>>(
        x3h, x3l, B3h, B3l, hw, (bf16*)0, (bf16*)0, N_NODES, HC, HC, (const float*)0, 2);
    scatter7_csr_kernel<<<SCAT_GRID, TB>>>(hw, x4h, x4l, rowptr, csr_r, csr_e, ea, dis, b3);

    // link head: UV = x4 @ Wuv
    gemm_mma_kernel<<<dim3(2, GRY), 256, MMA_SMEM>>>(
        x4h, x4l, Buvh, Buvl, UV, (bf16*)0, (bf16*)0, N_NODES, HC, 256, (const float*)0, 2);

    build_h0_kernel<<<cdiv((size_t)M2 * HLDIM, TB), TB>>>(UV, lb0, eit, Hah, Hal);

    const int GRY2 = cdiv(M2, 128);
    gemm_mma_kernel<<<dim3(1, GRY2), 256, MMA_SMEM>>>(
        Hah, Hal, Blhh, Blhl, (float*)0, Hbh, Hbl, M2, HLDIM, HLDIM, lbh, 1 | 4);
    gemm_mma_kernel<<<dim3(1, GRY2), 256, MMA_SMEM>>>(
        Hbh, Hbl, Blhh + HLDIM * HLDIM, Blhl + HLDIM * HLDIM, (float*)0, Hah, Hal,
        M2, HLDIM, HLDIM, lbh + HLDIM, 1 | 4);
    gemm_mma_kernel<<<dim3(1, GRY2), 256, MMA_SMEM>>>(
        Hah, Hal, Blhh + 2 * HLDIM * HLDIM, Blhl + 2 * HLDIM * HLDIM, Hbf, (bf16*)0, (bf16*)0,
        M2, HLDIM, HLDIM, lbh + 2 * HLDIM, 1 | 2);

    gemm_out_kernel<<<cdiv((size_t)M2 * 32, TB), TB>>>(Hbf, lw4, lb4, T, M2);
    combine_kernel<<<cdiv(ET_EDGES * 4, TB), TB>>>(T, out);
}

// round 11
// speedup vs baseline: 1.9191x; 1.0822x over previous
#include <cuda_runtime.h>
#include <cuda_bf16.h>
#include <stdint.h>
#include <math.h>

#define N_NODES 20000
#define E_EDGES 200000
#define ET_EDGES 40000
#define DIN 8
#define HDIM 128
#define NEA 7
#define HC 896
#define HLDIM 128
#define OUTD 4

typedef unsigned long long u64;
typedef unsigned int u32;
typedef __nv_bfloat16 bf16;

// ---------------- scratch ----------------
static __device__ float g_ew[E_EDGES];
static __device__ float g_dis[8 * N_NODES];
static __device__ float g_W0r[DIN * HC];
static __device__ float g_hw[(size_t)N_NODES * HC];
static __device__ float g_hw128[(size_t)N_NODES * HDIM];
static __device__ float g_UV[(size_t)N_NODES * 256];
static __device__ float g_Hb_f32[(size_t)2 * ET_EDGES * HLDIM];
static __device__ float g_T[(size_t)2 * ET_EDGES * OUTD];
static __device__ bf16 g_x1h[(size_t)N_NODES * HC];
static __device__ bf16 g_x1l[(size_t)N_NODES * HC];
static __device__ bf16 g_x2h[(size_t)N_NODES * HDIM];
static __device__ bf16 g_x2l[(size_t)N_NODES * HDIM];
static __device__ bf16 g_x3h[(size_t)N_NODES * HC];
static __device__ bf16 g_x3l[(size_t)N_NODES * HC];
static __device__ bf16 g_x4h[(size_t)N_NODES * HC];
static __device__ bf16 g_x4l[(size_t)N_NODES * HC];
static __device__ bf16 g_Hah[(size_t)2 * ET_EDGES * HLDIM];
static __device__ bf16 g_Hal[(size_t)2 * ET_EDGES * HLDIM];
static __device__ bf16 g_Hbh[(size_t)2 * ET_EDGES * HLDIM];
static __device__ bf16 g_Hbl[(size_t)2 * ET_EDGES * HLDIM];
static __device__ bf16 g_B1h[HDIM * HC];
static __device__ bf16 g_B1l[HDIM * HC];
static __device__ bf16 g_B2h[HC * HDIM];
static __device__ bf16 g_B2l[HC * HDIM];
static __device__ bf16 g_B3h[(size_t)HC * HC];
static __device__ bf16 g_B3l[(size_t)HC * HC];
static __device__ bf16 g_Buvh[256 * HC];
static __device__ bf16 g_Buvl[256 * HC];
static __device__ bf16 g_Blhh[3 * HLDIM * HLDIM];
static __device__ bf16 g_Blhl[3 * HLDIM * HLDIM];
static __device__ int g_cnt[N_NODES];
static __device__ int g_cursor[N_NODES];
static __device__ int g_rowptr[N_NODES + 1];
static __device__ int g_csr_r[E_EDGES];
static __device__ int g_csr_e[E_EDGES];

// ---------------- bf16 split helpers ----------------
__device__ __forceinline__ void split1(float v, bf16* ph, bf16* pl) {
    bf16 h = __float2bfloat16(v);
    *ph = h;
    *pl = __float2bfloat16(v - __bfloat162float(h));
}
__device__ __forceinline__ void split_store4(bf16* ph, bf16* pl, float4 v) {
    bf16 h0 = __float2bfloat16(v.x);
    bf16 h1 = __float2bfloat16(v.y);
    bf16 h2 = __float2bfloat16(v.z);
    bf16 h3 = __float2bfloat16(v.w);
    bf16 l0 = __float2bfloat16(v.x - __bfloat162float(h0));
    bf16 l1 = __float2bfloat16(v.y - __bfloat162float(h1));
    bf16 l2 = __float2bfloat16(v.z - __bfloat162float(h2));
    bf16 l3 = __float2bfloat16(v.w - __bfloat162float(h3));
    __nv_bfloat162* H = reinterpret_cast<__nv_bfloat162*>(ph);
    __nv_bfloat162* L = reinterpret_cast<__nv_bfloat162*>(pl);
    H[0] = __halves2bfloat162(h0, h1);
    H[1] = __halves2bfloat162(h2, h3);
    L[0] = __halves2bfloat162(l0, l1);
    L[1] = __halves2bfloat162(l2, l3);
}
__device__ __forceinline__ void split_store2(bf16* ph, bf16* pl, float x, float y) {
    bf16 hx = __float2bfloat16(x);
    bf16 hy = __float2bfloat16(y);
    bf16 lx = __float2bfloat16(x - __bfloat162float(hx));
    bf16 ly = __float2bfloat16(y - __bfloat162float(hy));
    *reinterpret_cast<__nv_bfloat162*>(ph) = __halves2bfloat162(hx, hy);
    *reinterpret_cast<__nv_bfloat162*>(pl) = __halves2bfloat162(lx, ly);
}

__device__ __forceinline__ u32 smem_u32(const void* p) {
    u32 a;
    asm("{ .reg .u64 t; cvta.to.shared.u64 t, %1; cvt.u32.u64 %0, t; }" : "=r"(a) : "l"(p));
    return a;
}

// ---------------- bf16 mma.sync GEMM with cp.async pipeline ----------------
// C[M,Nc] = A[M,K] @ B[Nc,K]^T, A/B as bf16 (hi,lo) pairs; AhBh+AhBl+AlBh, fp32 acc.
// flags: bit0 relu, bit1 write fp32 C, bit2 write bf16 pair CH/CL.
#define GBK 32
#define ASTR 40                  // padded smem row stride in bf16 (80B: 16B-aligned, conflict-free)
#define TSZ (128 * ASTR)
#define MMA_SMEM (2 * 4 * TSZ * 2)

#define MMA_BF16(d, a, b0v, b1v) \
    asm volatile("mma.sync.aligned.m16n8k16.row.col.f32.bf16.bf16.f32 " \
        "{%0,%1,%2,%3}, {%4,%5,%6,%7}, {%8,%9}, {%0,%1,%2,%3};" \
        : "+f"((d)[0]), "+f"((d)[1]), "+f"((d)[2]), "+f"((d)[3]) \
        : "r"((a)[0]), "r"((a)[1]), "r"((a)[2]), "r"((a)[3]), "r"(b0v), "r"(b1v))

#define CP_ASYNC16(dst_u32, src_ptr, nbytes) \
    asm volatile("cp.async.cg.shared.global [%0], [%1], 16, %2;" \
                 :: "r"(dst_u32), "l"(src_ptr), "r"(nbytes) : "memory")
#define CP_COMMIT() asm volatile("cp.async.commit_group;" ::: "memory")
#define CP_WAIT1()  asm volatile("cp.async.wait_group 1;" ::: "memory")
#define CP_WAIT0()  asm volatile("cp.async.wait_group 0;" ::: "memory")

__device__ __forceinline__ void gt_load_async(
    u32 smbase, int buf, int kb,
    const bf16* Ah, const bf16* Al, const bf16* Bh, const bf16* Bl,
    int rowBase, int colBase, int M, int K, int r0, int r1, int kv)
{
    u32 base = smbase + (u32)buf * 4 * TSZ * 2;
    u32 d00 = base + (u32)(0 * TSZ + r0 * ASTR + kv) * 2;
    u32 d01 = base + (u32)(0 * TSZ + r1 * ASTR + kv) * 2;
    u32 d10 = base + (u32)(1 * TSZ + r0 * ASTR + kv) * 2;
    u32 d11 = base + (u32)(1 * TSZ + r1 * ASTR + kv) * 2;
    u32 d20 = base + (u32)(2 * TSZ + r0 * ASTR + kv) * 2;
    u32 d21 = base + (u32)(2 * TSZ + r1 * ASTR + kv) * 2;
    u32 d30 = base + (u32)(3 * TSZ + r0 * ASTR + kv) * 2;
    u32 d31 = base + (u32)(3 * TSZ + r1 * ASTR + kv) * 2;
    size_t a0 = (size_t)(rowBase + r0) * K + kb + kv;
    size_t a1 = (size_t)(rowBase + r1) * K + kb + kv;
    int n0 = ((rowBase + r0) < M) ? 16 : 0;
    int n1 = ((rowBase + r1) < M) ? 16 : 0;
    CP_ASYNC16(d00, Ah + a0, n0);
    CP_ASYNC16(d01, Ah + a1, n1);
    CP_ASYNC16(d10, Al + a0, n0);
    CP_ASYNC16(d11, Al + a1, n1);
    size_t b0 = (size_t)(colBase + r0) * K + kb + kv;
    size_t b1 = (size_t)(colBase + r1) * K + kb + kv;
    CP_ASYNC16(d20, Bh + b0, 16);
    CP_ASYNC16(d21, Bh + b1, 16);
    CP_ASYNC16(d30, Bl + b0, 16);
    CP_ASYNC16(d31, Bl + b1, 16);
}

__global__ __launch_bounds__(256)
void gemm_mma_kernel(
    const bf16* __restrict__ Ah, const bf16* __restrict__ Al,
    const bf16* __restrict__ Bh, const bf16* __restrict__ Bl,
    float* __restrict__ C, bf16* __restrict__ CH, bf16* __restrict__ CL,
    int M, int K, int Nc, const float* __restrict__ bias, int flags)
{
    extern __shared__ bf16 sm[];
    const u32 smb = smem_u32(sm);
    const int tid = threadIdx.x;
    const int wid = tid >> 5;
    const int lane = tid & 31;
    const int rowBase = blockIdx.y * 128;
    const int colBase = blockIdx.x * 128;
    const int wRow = (wid & 3) * 32;
    const int wCol = (wid >> 2) * 64;
    const int ar = lane >> 2;
    const int ac = (lane & 3) << 1;

    const int lr0 = tid >> 2;
    const int lr1 = lr0 + 64;
    const int lkv = (tid & 3) << 3;

    float acc[2][8][4];
#pragma unroll
    for (int i = 0; i < 2; i++)
#pragma unroll
        for (int j = 0; j < 8; j++)
#pragma unroll
            for (int q = 0; q < 4; q++) acc[i][j][q] = 0.f;

    gt_load_async(smb, 0, 0, Ah, Al, Bh, Bl, rowBase, colBase, M, K, lr0, lr1, lkv);
    CP_COMMIT();

    const int NKB = K / GBK;
    int buf = 0;
    for (int kb = 0; kb < NKB; kb++) {
        const bool has = (kb + 1) < NKB;
        if (has) {
            gt_load_async(smb, buf ^ 1, (kb + 1) * GBK, Ah, Al, Bh, Bl,
                          rowBase, colBase, M, K, lr0, lr1, lkv);
            CP_COMMIT();
            CP_WAIT1();
        } else {
            CP_WAIT0();
        }
        __syncthreads();

        const bf16* base = sm + buf * 4 * TSZ;
#pragma unroll
        for (int ks = 0; ks < 2; ks++) {
            const int k0 = ks * 16;
            u32 afr[2][2][4];
#pragma unroll
            for (int rt = 0; rt < 2; rt++) {
#pragma unroll
                for (int h = 0; h < 2; h++) {
                    const bf16* p = base + h * TSZ + (wRow + rt * 16 + ar) * ASTR + k0 + ac;
                    afr[rt][h][0] = *(const u32*)p;
                    afr[rt][h][1] = *(const u32*)(p + 8 * ASTR);
                    afr[rt][h][2] = *(const u32*)(p + 8);
                    afr[rt][h][3] = *(const u32*)(p + 8 * ASTR + 8);
                }
            }
            u32 bfr[8][2][2];
#pragma unroll
            for (int ct = 0; ct < 8; ct++) {
                const bf16* q = base + 2 * TSZ + (wCol + ct * 8 + ar) * ASTR + k0 + ac;
                bfr[ct][0][0] = *(const u32*)q;
                bfr[ct][0][1] = *(const u32*)(q + 8);
                bfr[ct][1][0] = *(const u32*)(q + TSZ);
                bfr[ct][1][1] = *(const u32*)(q + TSZ + 8);
            }
            // product-separated: 16 independent accumulator chains per phase
#pragma unroll
            for (int ct = 0; ct < 8; ct++) {
#pragma unroll
                for (int rt = 0; rt < 2; rt++)
                    MMA_BF16(acc[rt][ct], afr[rt][0], bfr[ct][0][0], bfr[ct][0][1]);
            }
#pragma unroll
            for (int ct = 0; ct < 8; ct++) {
#pragma unroll
                for (int rt = 0; rt < 2; rt++)
                    MMA_BF16(acc[rt][ct], afr[rt][0], bfr[ct][1][0], bfr[ct][1][1]);
            }
#pragma unroll
            for (int ct = 0; ct < 8; ct++) {
#pragma unroll
                for (int rt = 0; rt < 2; rt++)
                    MMA_BF16(acc[rt][ct], afr[rt][1], bfr[ct][0][0], bfr[ct][0][1]);
            }
        }
        __syncthreads();
        buf ^= 1;
    }

    const int doRelu = flags & 1;
    const int wF = flags & 2;
    const int wP = flags & 4;
#pragma unroll
    for (int rt = 0; rt < 2; rt++) {
#pragma unroll
        for (int ct = 0; ct < 8; ct++) {
            int r = rowBase + wRow + rt * 16 + ar;
            int c = colBase + wCol + ct * 8 + ac;
            float b0v = bias ? __ldg(&bias[c]) : 0.f;
            float b1v = bias ? __ldg(&bias[c + 1]) : 0.f;
            float v0 = acc[rt][ct][0] + b0v;
            float v1 = acc[rt][ct][1] + b1v;
            float v2 = acc[rt][ct][2] + b0v;
            float v3 = acc[rt][ct][3] + b1v;
            if (doRelu) {
                v0 = fmaxf(v0, 0.f); v1 = fmaxf(v1, 0.f);
                v2 = fmaxf(v2, 0.f); v3 = fmaxf(v3, 0.f);
            }
            if (r < M) {
                size_t o = (size_t)r * Nc + c;
                if (wF) *(float2*)(C + o) = make_float2(v0, v1);
                if (wP) split_store2(CH + o, CL + o, v0, v1);
            }
            if (r + 8 < M) {
                size_t o = (size_t)(r + 8) * Nc + c;
                if (wF) *(float2*)(C + o) = make_float2(v2, v3);
                if (wP) split_store2(CH + o, CL + o, v2, v3);
            }
        }
    }
}

// ---------------- edge-weight MLP ----------------
__global__ __launch_bounds__(256) void edge_mlp_kernel(
    const float* __restrict__ ea,
    const float* __restrict__ w1, const float* __restrict__ bb1,
    const float* __restrict__ w2, const float* __restrict__ bb2,
    const float* __restrict__ w3, const float* __restrict__ bb3,
    float* __restrict__ out, int E)
{
    __shared__ float s1[NEA * 28];
    __shared__ float sb1[28];
    __shared__ float s2[28 * 28];
    __shared__ float sb2[28];
    __shared__ float s3[28];
    __shared__ float sb3v[1];
    for (int i = threadIdx.x; i < NEA * 28; i += blockDim.x) s1[i] = w1[i];
    for (int i = threadIdx.x; i < 28; i += blockDim.x) {
        sb1[i] = bb1[i];
        sb2[i] = bb2[i];
        s3[i] = w3[i];
    }
    for (int i = threadIdx.x; i < 28 * 28; i += blockDim.x) s2[i] = w2[i];
    if (threadIdx.x == 0) sb3v[0] = bb3[0];
    __syncthreads();

    int e = blockIdx.x * blockDim.x + threadIdx.x;
    if (e >= E) return;
    float a[NEA];
#pragma unroll
    for (int k = 0; k < NEA; k++) a[k] = ea[(size_t)e * NEA + k];
    float t[28];
#pragma unroll
    for (int j = 0; j < 28; j++) {
        float v = sb1[j];
#pragma unroll
        for (int k = 0; k < NEA; k++) v += a[k] * s1[k * 28 + j];
        t[j] = fmaxf(v, 0.f);
    }
    float u[28];
#pragma unroll
    for (int j = 0; j < 28; j++) {
        float v = sb2[j];
#pragma unroll
        for (int k = 0; k < 28; k++) v += t[k] * s2[k * 28 + j];
        u[j] = fmaxf(v, 0.f);
    }
    float z = sb3v[0];
#pragma unroll
    for (int k = 0; k < 28; k++) z += u[k] * s3[k];
    out[e] = 1.f / (1.f + expf(-z));
}

// ---------------- CSR build ----------------
__global__ void zero_int_kernel(int* __restrict__ p, int n) {
    int i = blockIdx.x * blockDim.x + threadIdx.x;
    if (i < n) p[i] = 0;
}
__global__ void count_kernel(const int* __restrict__ ei, int* __restrict__ cnt, int E) {
    int e = blockIdx.x * blockDim.x + threadIdx.x;
    if (e < E) atomicAdd(&cnt[ei[E + e]], 1);
}
__global__ __launch_bounds__(1024) void scan_kernel(
    const int* __restrict__ cnt, int* __restrict__ rowptr, int* __restrict__ cursor, int n)
{
    __shared__ int warpsum[32];
    const int t = threadIdx.x;
    const int lane = t & 31;
    const int wrp = t >> 5;
    const int C = (n + 1023) / 1024;
    const int base = t * C;
    int local = 0;
    for (int i = 0; i < C; i++) {
        int idx = base + i;
        if (idx < n) local += cnt[idx];
    }
    int sc = local;
#pragma unroll
    for (int off = 1; off < 32; off <<= 1) {
        int v = __shfl_up_sync(0xffffffffu, sc, off);
        if (lane >= off) sc += v;
    }
    if (lane == 31) warpsum[wrp] = sc;
    __syncthreads();
    if (wrp == 0) {
        int ws = warpsum[lane];
#pragma unroll
        for (int off = 1; off < 32; off <<= 1) {
            int v = __shfl_up_sync(0xffffffffu, ws, off);
            if (lane >= off) ws += v;
        }
        warpsum[lane] = ws;
    }
    __syncthreads();
    int run = (wrp > 0 ? warpsum[wrp - 1] : 0) + (sc - local);
    if (t == 0) rowptr[0] = 0;
    for (int i = 0; i < C; i++) {
        int idx = base + i;
        if (idx < n) {
            cursor[idx] = run;
            run += cnt[idx];
            rowptr[idx + 1] = run;
        }
    }
}
__global__ void csr_fill_kernel(const int* __restrict__ ei, int* __restrict__ cursor,
                                int* __restrict__ csr_r, int* __restrict__ csr_e, int E)
{
    int e = blockIdx.x * blockDim.x + threadIdx.x;
    if (e >= E) return;
    int r = ei[e];
    int c = ei[E + e];
    int pos = atomicAdd(&cursor[c], 1);
    csr_r[pos] = r;
    csr_e[pos] = e;
}

// ---------------- degrees via CSR ----------------
__global__ void deg_csr_kernel(const int* __restrict__ rowptr, const int* __restrict__ csr_e,
                               const float* __restrict__ ea, const float* __restrict__ ew,
                               float* __restrict__ dis)
{
    int idx = blockIdx.x * blockDim.x + threadIdx.x;
    if (idx >= 8 * N_NODES) return;
    int i = idx / N_NODES;
    int v = idx % N_NODES;
    int p0 = rowptr[v];
    int p1 = rowptr[v + 1];
    float s = 1.0f;
    if (i < NEA) {
        for (int p = p0; p < p1; p++) s += __ldg(&ea[(size_t)csr_e[p] * NEA + i]);
    } else {
        for (int p = p0; p < p1; p++) s += __ldg(&ew[csr_e[p]]);
    }
    dis[idx] = rsqrtf(s);
}

// ---------------- weight packs ----------------
__global__ void pack_w_kernel(const float* __restrict__ in, float* __restrict__ out, int K) {
    int idx = blockIdx.x * blockDim.x + threadIdx.x;
    if (idx >= K * HC) return;
    int k = idx / HC;
    int c = idx % HC;
    int i = c >> 7;
    int j = c & 127;
    out[idx] = in[((size_t)i * K + k) * HDIM + j];
}
__global__ void pack_b1_kernel(const float* __restrict__ W1, bf16* __restrict__ Bh, bf16* __restrict__ Bl) {
    int idx = blockIdx.x * blockDim.x + threadIdx.x;
    if (idx >= HDIM * HC) return;
    int n = idx / HC;
    int k = idx % HC;
    split1(W1[(size_t)k * HDIM + n], &Bh[idx], &Bl[idx]);
}
__global__ void pack_b2_kernel(const float* __restrict__ W2, bf16* __restrict__ Bh, bf16* __restrict__ Bl) {
    int idx = blockIdx.x * blockDim.x + threadIdx.x;
    if (idx >= HC * HDIM) return;
    int c = idx / HDIM;
    int k = idx % HDIM;
    int i = c >> 7;
    int j = c & 127;
    split1(W2[((size_t)i * HDIM + k) * HDIM + j], &Bh[idx], &Bl[idx]);
}
__global__ void pack_b3_kernel(const float* __restrict__ W3, bf16* __restrict__ Bh, bf16* __restrict__ Bl) {
    int idx = blockIdx.x * blockDim.x + threadIdx.x;
    if (idx >= HC * HC) return;
    int c = idx / HC;
    int k = idx % HC;
    int i = c >> 7;
    int j = c & 127;
    split1(W3[((size_t)i * HC + k) * HDIM + j], &Bh[idx], &Bl[idx]);
}
__global__ void pack_buv_kernel(const float* __restrict__ lw0, bf16* __restrict__ Bh, bf16* __restrict__ Bl) {
    int idx = blockIdx.x * blockDim.x + threadIdx.x;
    if (idx >= 256 * HC) return;
    int c = idx / HC;
    int k = idx % HC;
    float v = (c < 128) ? lw0[(size_t)k * 128 + c] : lw0[(size_t)(HC + k) * 128 + (c - 128)];
    split1(v, &Bh[idx], &Bl[idx]);
}
__global__ void pack_blh_kernel(const float* __restrict__ lwh, bf16* __restrict__ Bh, bf16* __restrict__ Bl) {
    int idx = blockIdx.x * blockDim.x + threadIdx.x;
    if (idx >= 3 * HLDIM * HLDIM) return;
    int i = idx / (HLDIM * HLDIM);
    int n = (idx / HLDIM) % HLDIM;
    int k = idx % HLDIM;
    split1(lwh[((size_t)i * HLDIM + k) * HLDIM + n], &Bh[idx], &Bl[idx]);
}

// ---------------- G0: x[N,8] @ W0r[8,896] (fp32) ----------------
__global__ void gemm_k8_kernel(const float* __restrict__ x, const float* __restrict__ W,
                               float* __restrict__ out)
{
    int idx = blockIdx.x * blockDim.x + threadIdx.x;
    if (idx >= N_NODES * HC) return;
    int m = idx / HC;
    int c = idx % HC;
    float v = 0.f;
#pragma unroll
    for (int k = 0; k < DIN; k++) v += __ldg(&x[m * DIN + k]) * W[k * HC + c];
    out[idx] = v;
}

// ---------------- CSR scatter, channel-split: one warp per (node, channel) ----------------
__global__ __launch_bounds__(256) void scatter7_csr_kernel(
    const float* __restrict__ hw, bf16* __restrict__ outH, bf16* __restrict__ outL,
    const int* __restrict__ rowptr, const int* __restrict__ csr_r, const int* __restrict__ csr_e,
    const float* __restrict__ ea, const float* __restrict__ dis,
    const float* __restrict__ bias)
{
    int w = (blockIdx.x * blockDim.x + threadIdx.x) >> 5;
    int lane = threadIdx.x & 31;
    if (w >= N_NODES * NEA) return;
    int i = w % NEA;
    int c = w / NEA;

    float dc = __ldg(&dis[i * N_NODES + c]);
    float4 acc;
    {
        float4 v = *(const float4*)(hw + (size_t)c * HC + i * HDIM + lane * 4);
        float4 b = *(const float4*)(bias + i * HDIM + lane * 4);
        float s = dc * dc;
        acc.x = b.x + s * v.x;
        acc.y = b.y + s * v.y;
        acc.z = b.z + s * v.z;
        acc.w = b.w + s * v.w;
    }

    int p0 = __ldg(&rowptr[c]);
    int p1 = __ldg(&rowptr[c + 1]);
    if (p0 < p1) {
        int r = __ldg(&csr_r[p0]);
        int e = __ldg(&csr_e[p0]);
        for (int p = p0; p < p1; p++) {
            int rn = 0, en = 0;
            if (p + 1 < p1) {
                rn = __ldg(&csr_r[p + 1]);
                en = __ldg(&csr_e[p + 1]);
            }
            float co = __ldg(&dis[i * N_NODES + r]) * dc * __ldg(&ea[(size_t)e * NEA + i]);
            float4 v = *(const float4*)(hw + (size_t)r * HC + i * HDIM + lane * 4);
            acc.x += co * v.x;
            acc.y += co * v.y;
            acc.z += co * v.z;
            acc.w += co * v.w;
            r = rn;
            e = en;
        }
    }

    acc.x = fmaxf(acc.x, 0.f);
    acc.y = fmaxf(acc.y, 0.f);
    acc.z = fmaxf(acc.z, 0.f);
    acc.w = fmaxf(acc.w, 0.f);
    size_t o = (size_t)c * HC + i * HDIM + lane * 4;
    split_store4(outH + o, outL + o, acc);
}

// ---------------- CSR scatter, single channel -> bf16 pair ----------------
__global__ __launch_bounds__(256) void scatter1_csr_kernel(
    const float* __restrict__ hw, bf16* __restrict__ outH, bf16* __restrict__ outL,
    const int* __restrict__ rowptr, const int* __restrict__ csr_r, const int* __restrict__ csr_e,
    const float* __restrict__ ewv, const float* __restrict__ dis7,
    const float* __restrict__ bias)
{
    int c = (blockIdx.x * blockDim.x + threadIdx.x) >> 5;
    int lane = threadIdx.x & 31;
    if (c >= N_NODES) return;

    float dc = __ldg(&dis7[c]);
    float4 acc;
    {
        float4 v = *(const float4*)(hw + (size_t)c * HDIM + lane * 4);
        float4 b = *(const float4*)(bias + lane * 4);
        float s = dc * dc;
        acc.x = b.x + s * v.x;
        acc.y = b.y + s * v.y;
        acc.z = b.z + s * v.z;
        acc.w = b.w + s * v.w;
    }
    int p0 = __ldg(&rowptr[c]);
    int p1 = __ldg(&rowptr[c + 1]);
    if (p0 < p1) {
        int r = __ldg(&csr_r[p0]);
        int e = __ldg(&csr_e[p0]);
        for (int p = p0; p < p1; p++) {
            int rn = 0, en = 0;
            if (p + 1 < p1) {
                rn = __ldg(&csr_r[p + 1]);
                en = __ldg(&csr_e[p + 1]);
            }
            float co = __ldg(&dis7[r]) * dc * __ldg(&ewv[e]);
            float4 v = *(const float4*)(hw + (size_t)r * HDIM + lane * 4);
            acc.x += co * v.x;
            acc.y += co * v.y;
            acc.z += co * v.z;
            acc.w += co * v.w;
            r = rn;
            e = en;
        }
    }
    acc.x = fmaxf(acc.x, 0.f);
    acc.y = fmaxf(acc.y, 0.f);
    acc.z = fmaxf(acc.z, 0.f);
    acc.w = fmaxf(acc.w, 0.f);
    size_t o = (size_t)c * HDIM + lane * 4;
    split_store4(outH + o, outL + o, acc);
}

// ---------------- link head ----------------
__global__ void build_h0_kernel(const float* __restrict__ UV,
                                const float* __restrict__ lb0, const int* __restrict__ eit,
                                bf16* __restrict__ Hh, bf16* __restrict__ Hl)
{
    size_t idx = (size_t)blockIdx.x * blockDim.x + threadIdx.x;
    if (idx >= (size_t)2 * ET_EDGES * HLDIM) return;
    int e = (int)(idx >> 7);
    int j = (int)(idx & 127);
    int a;
    int b;
    if (e < ET_EDGES) {
        a = eit[e];
        b = eit[ET_EDGES + e];
    } else {
        int e2 = e - ET_EDGES;
        a = eit[ET_EDGES + e2];
        b = eit[e2];
    }
    float v = UV[(size_t)a * 256 + j] + UV[(size_t)b * 256 + 128 + j] + lb0[j];
    v = fmaxf(v, 0.f);
    split1(v, &Hh[idx], &Hl[idx]);
}

__global__ __launch_bounds__(256) void gemm_out_kernel(
    const float* __restrict__ Hm, const float* __restrict__ lw4,
    const float* __restrict__ lb4, float* __restrict__ T, int M)
{
    int w = (blockIdx.x * blockDim.x + threadIdx.x) >> 5;
    int lane = threadIdx.x & 31;
    if (w >= M) return;
    float h0 = Hm[(size_t)w * HLDIM + lane];
    float h1 = Hm[(size_t)w * HLDIM + 32 + lane];
    float h2 = Hm[(size_t)w * HLDIM + 64 + lane];
    float h3 = Hm[(size_t)w * HLDIM + 96 + lane];
    float acc[4];
#pragma unroll
    for (int c = 0; c < 4; c++) {
        acc[c] = h0 * __ldg(&lw4[lane * 4 + c])
               + h1 * __ldg(&lw4[(lane + 32) * 4 + c])
               + h2 * __ldg(&lw4[(lane + 64) * 4 + c])
               + h3 * __ldg(&lw4[(lane + 96) * 4 + c]);
    }
#pragma unroll
    for (int off = 16; off > 0; off >>= 1) {
#pragma unroll
        for (int c = 0; c < 4; c++) acc[c] += __shfl_down_sync(0xffffffffu, acc[c], off);
    }
    if (lane == 0) {
#pragma unroll
        for (int c = 0; c < 4; c++) T[(size_t)w * 4 + c] = acc[c] + lb4[c];
    }
}

__global__ void combine_kernel(const float* __restrict__ T, float* __restrict__ out) {
    int idx = blockIdx.x * blockDim.x + threadIdx.x;
    if (idx >= ET_EDGES * 4) return;
    int e = idx >> 2;
    int c = idx & 3;
    int pc = (c == 1) ? 2 : ((c == 2) ? 1 : c);
    out[idx] = 0.5f * (T[(size_t)e * 4 + c] + T[(size_t)(ET_EDGES + e) * 4 + pc]);
}

// ---------------- host orchestration ----------------
static inline int cdiv(size_t a, int b) { return (int)((a + b - 1) / b); }

extern "C" void kernel_launch(void* const* d_in, const int* in_sizes, int n_in,
                              void* d_out, int out_size)
{
    const float* x    = (const float*)d_in[0];
    const int*   ei   = (const int*)  d_in[1];
    const float* ea   = (const float*)d_in[2];
    const int*   eit  = (const int*)  d_in[3];
    const float* W0   = (const float*)d_in[4];
    const float* b0   = (const float*)d_in[5];
    const float* W1   = (const float*)d_in[6];
    const float* b1   = (const float*)d_in[7];
    const float* W2   = (const float*)d_in[8];
    const float* b2   = (const float*)d_in[9];
    const float* W3   = (const float*)d_in[10];
    const float* b3   = (const float*)d_in[11];
    const float* ew1  = (const float*)d_in[12];
    const float* eb1  = (const float*)d_in[13];
    const float* ew2  = (const float*)d_in[14];
    const float* eb2  = (const float*)d_in[15];
    const float* ew3  = (const float*)d_in[16];
    const float* eb3  = (const float*)d_in[17];
    const float* lw0  = (const float*)d_in[18];
    const float* lb0  = (const float*)d_in[19];
    const float* lwh  = (const float*)d_in[20];
    const float* lbh  = (const float*)d_in[21];
    const float* lw4  = (const float*)d_in[22];
    const float* lb4  = (const float*)d_in[23];
    float* out = (float*)d_out;

    float *ew, *dis, *W0r, *hw, *hw128, *UV, *Hbf, *T;
    bf16 *x1h, *x1l, *x2h, *x2l, *x3h, *x3l, *x4h, *x4l;
    bf16 *Hah, *Hal, *Hbh, *Hbl;
    bf16 *B1h, *B1l, *B2h, *B2l, *B3h, *B3l, *Buvh, *Buvl, *Blhh, *Blhl;
    int *cnt, *cursor, *rowptr, *csr_r, *csr_e;
    cudaGetSymbolAddress((void**)&ew,    g_ew);
    cudaGetSymbolAddress((void**)&dis,   g_dis);
    cudaGetSymbolAddress((void**)&W0r,   g_W0r);
    cudaGetSymbolAddress((void**)&hw,    g_hw);
    cudaGetSymbolAddress((void**)&hw128, g_hw128);
    cudaGetSymbolAddress((void**)&UV,    g_UV);
    cudaGetSymbolAddress((void**)&Hbf,   g_Hb_f32);
    cudaGetSymbolAddress((void**)&T,     g_T);
    cudaGetSymbolAddress((void**)&x1h,   g_x1h);
    cudaGetSymbolAddress((void**)&x1l,   g_x1l);
    cudaGetSymbolAddress((void**)&x2h,   g_x2h);
    cudaGetSymbolAddress((void**)&x2l,   g_x2l);
    cudaGetSymbolAddress((void**)&x3h,   g_x3h);
    cudaGetSymbolAddress((void**)&x3l,   g_x3l);
    cudaGetSymbolAddress((void**)&x4h,   g_x4h);
    cudaGetSymbolAddress((void**)&x4l,   g_x4l);
    cudaGetSymbolAddress((void**)&Hah,   g_Hah);
    cudaGetSymbolAddress((void**)&Hal,   g_Hal);
    cudaGetSymbolAddress((void**)&Hbh,   g_Hbh);
    cudaGetSymbolAddress((void**)&Hbl,   g_Hbl);
    cudaGetSymbolAddress((void**)&B1h,   g_B1h);
    cudaGetSymbolAddress((void**)&B1l,   g_B1l);
    cudaGetSymbolAddress((void**)&B2h,   g_B2h);
    cudaGetSymbolAddress((void**)&B2l,   g_B2l);
    cudaGetSymbolAddress((void**)&B3h,   g_B3h);
    cudaGetSymbolAddress((void**)&B3l,   g_B3l);
    cudaGetSymbolAddress((void**)&Buvh,  g_Buvh);
    cudaGetSymbolAddress((void**)&Buvl,  g_Buvl);
    cudaGetSymbolAddress((void**)&Blhh,  g_Blhh);
    cudaGetSymbolAddress((void**)&Blhl,  g_Blhl);
    cudaGetSymbolAddress((void**)&cnt,   g_cnt);
    cudaGetSymbolAddress((void**)&cursor,g_cursor);
    cudaGetSymbolAddress((void**)&rowptr,g_rowptr);
    cudaGetSymbolAddress((void**)&csr_r, g_csr_r);
    cudaGetSymbolAddress((void**)&csr_e, g_csr_e);

    cudaFuncSetAttribute(gemm_mma_kernel, cudaFuncAttributeMaxDynamicSharedMemorySize, MMA_SMEM);

    const int TB = 256;
    const size_t NW = (size_t)N_NODES * HC;
    const int M2 = 2 * ET_EDGES;

    edge_mlp_kernel<<<cdiv(E_EDGES, TB), TB>>>(ea, ew1, eb1, ew2, eb2, ew3, eb3, ew, E_EDGES);

    zero_int_kernel<<<cdiv(N_NODES, TB), TB>>>(cnt, N_NODES);
    count_kernel<<<cdiv(E_EDGES, TB), TB>>>(ei, cnt, E_EDGES);
    scan_kernel<<<1, 1024>>>(cnt, rowptr, cursor, N_NODES);
    csr_fill_kernel<<<cdiv(E_EDGES, TB), TB>>>(ei, cursor, csr_r, csr_e, E_EDGES);

    deg_csr_kernel<<<cdiv(8 * N_NODES, TB), TB>>>(rowptr, csr_e, ea, ew, dis);

    pack_w_kernel<<<cdiv(DIN * HC, TB), TB>>>(W0, W0r, DIN);
    pack_b1_kernel<<<cdiv(HDIM * HC, TB), TB>>>(W1, B1h, B1l);
    pack_b2_kernel<<<cdiv(HC * HDIM, TB), TB>>>(W2, B2h, B2l);
    pack_b3_kernel<<<cdiv((size_t)HC * HC, TB), TB>>>(W3, B3h, B3l);
    pack_buv_kernel<<<cdiv(256 * HC, TB), TB>>>(lw0, Buvh, Buvl);
    pack_blh_kernel<<<cdiv(3 * HLDIM * HLDIM, TB), TB>>>(lwh, Blhh, Blhl);

    const int SCAT7_GRID = cdiv((size_t)N_NODES * NEA * 32, TB);
    const int SCAT1_GRID = cdiv((size_t)N_NODES * 32, TB);
    const int GRY = cdiv(N_NODES, 128);

    // layer 1
    gemm_k8_kernel<<<cdiv(NW, TB), TB>>>(x, W0r, hw);
    scatter7_csr_kernel<<<SCAT7_GRID, TB>>>(hw, x1h, x1l, rowptr, csr_r, csr_e, ea, dis, b0);

    // layer 2
    gemm_mma_kernel<<<dim3(1, GRY), 256, MMA_SMEM>>>(
        x1h, x1l, B1h, B1l, hw128, (bf16*)0, (bf16*)0, N_NODES, HC, HDIM, (const float*)0, 2);
    scatter1_csr_kernel<<<SCAT1_GRID, TB>>>(hw128, x2h, x2l, rowptr, csr_r, csr_e, ew,
                                            dis + NEA * N_NODES, b1);

    // layer 3
    gemm_mma_kernel<<<dim3(7, GRY), 256, MMA_SMEM>>>(
        x2h, x2l, B2h, B2l, hw, (bf16*)0, (bf16*)0, N_NODES, HDIM, HC, (const float*)0, 2);
    scatter7_csr_kernel<<<SCAT7_GRID, TB>>>(hw, x3h, x3l, rowptr, csr_r, csr_e, ea, dis, b2);

    // layer 4
    gemm_mma_kernel<<<dim3(7, GRY), 256, MMA_SMEM>>>(
        x3h, x3l, B3h, B3l, hw, (bf16*)0, (bf16*)0, N_NODES, HC, HC, (const float*)0, 2);
    scatter7_csr_kernel<<<SCAT7_GRID, TB>>>(hw, x4h, x4l, rowptr, csr_r, csr_e, ea, dis, b3);

    // link head: UV = x4 @ Wuv
    gemm_mma_kernel<<<dim3(2, GRY), 256, MMA_SMEM>>>(
        x4h, x4l, Buvh, Buvl, UV, (bf16*)0, (bf16*)0, N_NODES, HC, 256, (const float*)0, 2);

    build_h0_kernel<<<cdiv((size_t)M2 * HLDIM, TB), TB>>>(UV, lb0, eit, Hah, Hal);

    const int GRY2 = cdiv(M2, 128);
    gemm_mma_kernel<<<dim3(1, GRY2), 256, MMA_SMEM>>>(
        Hah, Hal, Blhh, Blhl, (float*)0, Hbh, Hbl, M2, HLDIM, HLDIM, lbh, 1 | 4);
    gemm_mma_kernel<<<dim3(1, GRY2), 256, MMA_SMEM>>>(
        Hbh, Hbl, Blhh + HLDIM * HLDIM, Blhl + HLDIM * HLDIM, (float*)0, Hah, Hal,
        M2, HLDIM, HLDIM, lbh + HLDIM, 1 | 4);
    gemm_mma_kernel<<<dim3(1, GRY2), 256, MMA_SMEM>>>(
        Hah, Hal, Blhh + 2 * HLDIM * HLDIM, Blhl + 2 * HLDIM * HLDIM, Hbf, (bf16*)0, (bf16*)0,
        M2, HLDIM, HLDIM, lbh + 2 * HLDIM, 1 | 2);

    gemm_out_kernel<<<cdiv((size_t)M2 * 32, TB), TB>>>(Hbf, lw4, lb4, T, M2);
    combine_kernel<<<cdiv(ET_EDGES * 4, TB), TB>>>(T, out);
}